// round 2
// baseline (speedup 1.0000x reference)
#include <cuda_runtime.h>
#include <math.h>

#define BB 4
#define NN 1024
#define CC 1024
#define HH 16
#define DH 64
#define MROWS (BB*NN)   // 4096

// ---------------- scratch (device globals; no allocation allowed) ----------
__device__ float g_pre[MROWS*CC];          // 16 MB
__device__ float g_q[BB*HH*NN*DH];         // 16 MB
__device__ float g_k[BB*HH*NN*DH];         // 16 MB
__device__ float g_v[BB*HH*NN*DH];         // 16 MB
__device__ float g_logits[BB*NN*NN];       // 16 MB
__device__ float g_ctx[MROWS*CC];          // 16 MB

enum { MODE_SILU = 0, MODE_BHND = 1, MODE_RESID = 2 };

// ---------------------------------------------------------------------------
// Generic 64x64-tile fp32 GEMM: C = A[M,K] @ W[K,1024], with epilogues.
//   MODE_SILU : C = silu(A@W + bias), row-major [M,1024]
//   MODE_BHND : C = A@W scattered to [B,H,N,Dh]  (col tile == one head)
//   MODE_RESID: C = A@W + bias + resid, row-major
// 256 threads, 4x4 accum per thread, K-tile 16.
// ---------------------------------------------------------------------------
__global__ __launch_bounds__(256) void gemm64(
    const float* __restrict__ A, const float* __restrict__ W,
    const float* __restrict__ bias, const float* __restrict__ resid,
    float* __restrict__ C, int K, int mode)
{
    __shared__ float As[16][68];   // k-major: As[kk][row]
    __shared__ float Ws[16][68];   // Ws[kk][col]

    const int t   = threadIdx.x;
    const int r4  = t >> 4;        // 0..15 -> rows 4*r4..4*r4+3
    const int c4  = t & 15;        // 0..15 -> cols 4*c4..4*c4+3
    const int row0 = blockIdx.y * 64;
    const int col0 = blockIdx.x * 64;

    const int lr = t >> 2;         // A-load row within tile (0..63)
    const int lk = (t & 3) * 4;    // A-load k offset
    const int wk = t >> 4;         // W-load k row (0..15)
    const int wc = (t & 15) * 4;   // W-load col offset

    float acc[4][4] = {};

    for (int k0 = 0; k0 < K; k0 += 16) {
        float4 av = *(const float4*)&A[(size_t)(row0 + lr) * K + k0 + lk];
        As[lk + 0][lr] = av.x; As[lk + 1][lr] = av.y;
        As[lk + 2][lr] = av.z; As[lk + 3][lr] = av.w;
        *(float4*)&Ws[wk][wc] = *(const float4*)&W[(size_t)(k0 + wk) * CC + col0 + wc];
        __syncthreads();
#pragma unroll
        for (int kk = 0; kk < 16; kk++) {
            float4 a = *(const float4*)&As[kk][r4 * 4];
            float4 b = *(const float4*)&Ws[kk][c4 * 4];
            float ar[4] = {a.x, a.y, a.z, a.w};
            float br[4] = {b.x, b.y, b.z, b.w};
#pragma unroll
            for (int i = 0; i < 4; i++)
#pragma unroll
                for (int j = 0; j < 4; j++)
                    acc[i][j] += ar[i] * br[j];
        }
        __syncthreads();
    }

    if (mode == MODE_BHND) {
        const int b = row0 >> 10;          // tile stays within one batch (64 | 1024)
        const int h = col0 >> 6;           // 64-wide col tile == one head
        float* outp = C + ((size_t)(b * HH + h)) * NN * DH;
#pragma unroll
        for (int i = 0; i < 4; i++) {
            const int n = (row0 & (NN - 1)) + r4 * 4 + i;
            float4 o = make_float4(acc[i][0], acc[i][1], acc[i][2], acc[i][3]);
            *(float4*)&outp[n * DH + c4 * 4] = o;
        }
    } else {
        const float4 bv = *(const float4*)&bias[col0 + c4 * 4];
        const float bb[4] = {bv.x, bv.y, bv.z, bv.w};
#pragma unroll
        for (int i = 0; i < 4; i++) {
            const int row = row0 + r4 * 4 + i;
            float o[4];
#pragma unroll
            for (int j = 0; j < 4; j++) o[j] = acc[i][j] + bb[j];
            if (mode == MODE_SILU) {
#pragma unroll
                for (int j = 0; j < 4; j++) o[j] = o[j] / (1.0f + __expf(-o[j]));
            } else { // MODE_RESID
                const float4 rv = *(const float4*)&resid[(size_t)row * CC + col0 + c4 * 4];
                o[0] += rv.x; o[1] += rv.y; o[2] += rv.z; o[3] += rv.w;
            }
            *(float4*)&C[(size_t)row * CC + col0 + c4 * 4] =
                make_float4(o[0], o[1], o[2], o[3]);
        }
    }
}

// ---------------------------------------------------------------------------
// logits[b,n,m] = (pre[b,n,:] . pre[b,m,:]) / 32       (A @ A^T per batch)
// ---------------------------------------------------------------------------
__global__ __launch_bounds__(256) void logits_k(
    const float* __restrict__ pre, float* __restrict__ L)
{
    __shared__ float As[16][68];
    __shared__ float Bs[16][68];

    const int t  = threadIdx.x;
    const int r4 = t >> 4, c4 = t & 15;
    const int b  = blockIdx.z;
    const float* P = pre + (size_t)b * NN * CC;
    const int n0 = blockIdx.y * 64;
    const int m0 = blockIdx.x * 64;

    const int lr = t >> 2;
    const int lk = (t & 3) * 4;

    float acc[4][4] = {};

    for (int k0 = 0; k0 < CC; k0 += 16) {
        float4 av = *(const float4*)&P[(size_t)(n0 + lr) * CC + k0 + lk];
        As[lk + 0][lr] = av.x; As[lk + 1][lr] = av.y;
        As[lk + 2][lr] = av.z; As[lk + 3][lr] = av.w;
        float4 bv = *(const float4*)&P[(size_t)(m0 + lr) * CC + k0 + lk];
        Bs[lk + 0][lr] = bv.x; Bs[lk + 1][lr] = bv.y;
        Bs[lk + 2][lr] = bv.z; Bs[lk + 3][lr] = bv.w;
        __syncthreads();
#pragma unroll
        for (int kk = 0; kk < 16; kk++) {
            float4 a = *(const float4*)&As[kk][r4 * 4];
            float4 c = *(const float4*)&Bs[kk][c4 * 4];
            float ar[4] = {a.x, a.y, a.z, a.w};
            float br[4] = {c.x, c.y, c.z, c.w};
#pragma unroll
            for (int i = 0; i < 4; i++)
#pragma unroll
                for (int j = 0; j < 4; j++)
                    acc[i][j] += ar[i] * br[j];
        }
        __syncthreads();
    }

    float* out = L + (size_t)b * NN * NN;
#pragma unroll
    for (int i = 0; i < 4; i++) {
        const int n = n0 + r4 * 4 + i;
        float4 o = make_float4(acc[i][0] * 0.03125f, acc[i][1] * 0.03125f,
                               acc[i][2] * 0.03125f, acc[i][3] * 0.03125f);
        *(float4*)&out[(size_t)n * NN + m0 + c4 * 4] = o;
    }
}

// ---------------------------------------------------------------------------
// Flash attention with additive bias pi*logits.
// grid = (N/64 query tiles, B*H). 256 threads; thread owns 4 rows x 4 cols.
// Row-group = 16 consecutive lanes -> shuffle reductions (xor 1,2,4,8).
// smem: Qt/Kt d-major [64][68], Vs m-major [64][68], Ps [64][68].
// FIX (R2): 64x64 tiles are 4096 floats -> each of 256 threads must load
//           4 float4s (row lr, d = (t&3)*16 + {0,4,8,12}), not 1.
// ---------------------------------------------------------------------------
#define TPITCH 68
#define SMEM_ATTN (4 * 64 * TPITCH * (int)sizeof(float))

__global__ __launch_bounds__(256) void attn_k(
    const float* __restrict__ q, const float* __restrict__ k,
    const float* __restrict__ v, const float* __restrict__ logits,
    const float* __restrict__ pi_p, float* __restrict__ ctx)
{
    extern __shared__ float sm[];
    float* Qt = sm;
    float* Kt = sm + 64 * TPITCH;
    float* Vs = sm + 2 * 64 * TPITCH;
    float* Ps = sm + 3 * 64 * TPITCH;

    const int t  = threadIdx.x;
    const int r4 = t >> 4, c4 = t & 15;
    const int bh = blockIdx.y;
    const int b  = bh >> 4;
    const int h  = bh & 15;
    const int qi0 = blockIdx.x * 64;

    const float* qb = q + (size_t)bh * NN * DH;
    const float* kb = k + (size_t)bh * NN * DH;
    const float* vb = v + (size_t)bh * NN * DH;
    const float* lg = logits + (size_t)b * NN * NN + (size_t)qi0 * NN;
    const float pi = pi_p[0];

    const int lr  = t >> 2;          // tile row 0..63
    const int ld0 = (t & 3) * 16;    // d-base: 4 threads cover 64 d's

    { // load Q tile transposed (d-major): full 64x64
#pragma unroll
        for (int c = 0; c < 4; c++) {
            const int d = ld0 + c * 4;
            float4 qv = *(const float4*)&qb[(size_t)(qi0 + lr) * DH + d];
            Qt[(d + 0) * TPITCH + lr] = qv.x; Qt[(d + 1) * TPITCH + lr] = qv.y;
            Qt[(d + 2) * TPITCH + lr] = qv.z; Qt[(d + 3) * TPITCH + lr] = qv.w;
        }
    }

    float m_i[4], l_i[4], O[4][4];
#pragma unroll
    for (int i = 0; i < 4; i++) {
        m_i[i] = -1e30f; l_i[i] = 0.0f;
#pragma unroll
        for (int j = 0; j < 4; j++) O[i][j] = 0.0f;
    }

    for (int kt = 0; kt < 16; kt++) {
        const int mm0 = kt * 64;
        __syncthreads();   // prior iter's Ps/Vs consumers done
        {
#pragma unroll
            for (int c = 0; c < 4; c++) {
                const int d = ld0 + c * 4;
                float4 kv = *(const float4*)&kb[(size_t)(mm0 + lr) * DH + d];
                Kt[(d + 0) * TPITCH + lr] = kv.x; Kt[(d + 1) * TPITCH + lr] = kv.y;
                Kt[(d + 2) * TPITCH + lr] = kv.z; Kt[(d + 3) * TPITCH + lr] = kv.w;
                *(float4*)&Vs[lr * TPITCH + d] =
                    *(const float4*)&vb[(size_t)(mm0 + lr) * DH + d];
            }
        }
        __syncthreads();   // tiles (and Qt on first iter) visible

        float s[4][4] = {};
#pragma unroll 8
        for (int d = 0; d < 64; d++) {
            float4 a = *(const float4*)&Qt[d * TPITCH + r4 * 4];
            float4 c = *(const float4*)&Kt[d * TPITCH + c4 * 4];
            float ar[4] = {a.x, a.y, a.z, a.w};
            float br[4] = {c.x, c.y, c.z, c.w};
#pragma unroll
            for (int i = 0; i < 4; i++)
#pragma unroll
                for (int j = 0; j < 4; j++)
                    s[i][j] += ar[i] * br[j];
        }

#pragma unroll
        for (int i = 0; i < 4; i++) {
            // add bias:  s = qk/8 + pi * logits
            float4 Lr = *(const float4*)&lg[(size_t)(r4 * 4 + i) * NN + mm0 + c4 * 4];
            s[i][0] = s[i][0] * 0.125f + pi * Lr.x;
            s[i][1] = s[i][1] * 0.125f + pi * Lr.y;
            s[i][2] = s[i][2] * 0.125f + pi * Lr.z;
            s[i][3] = s[i][3] * 0.125f + pi * Lr.w;

            // online softmax
            float tm = fmaxf(fmaxf(s[i][0], s[i][1]), fmaxf(s[i][2], s[i][3]));
            tm = fmaxf(tm, __shfl_xor_sync(0xffffffffu, tm, 1));
            tm = fmaxf(tm, __shfl_xor_sync(0xffffffffu, tm, 2));
            tm = fmaxf(tm, __shfl_xor_sync(0xffffffffu, tm, 4));
            tm = fmaxf(tm, __shfl_xor_sync(0xffffffffu, tm, 8));
            const float mn   = fmaxf(m_i[i], tm);
            const float alpha = __expf(m_i[i] - mn);
            m_i[i] = mn;

            float ps = 0.0f;
#pragma unroll
            for (int j = 0; j < 4; j++) {
                s[i][j] = __expf(s[i][j] - mn);
                ps += s[i][j];
            }
            ps += __shfl_xor_sync(0xffffffffu, ps, 1);
            ps += __shfl_xor_sync(0xffffffffu, ps, 2);
            ps += __shfl_xor_sync(0xffffffffu, ps, 4);
            ps += __shfl_xor_sync(0xffffffffu, ps, 8);
            l_i[i] = l_i[i] * alpha + ps;
#pragma unroll
            for (int j = 0; j < 4; j++) O[i][j] *= alpha;

            *(float4*)&Ps[(r4 * 4 + i) * TPITCH + c4 * 4] =
                make_float4(s[i][0], s[i][1], s[i][2], s[i][3]);
        }
        __syncthreads();   // Ps visible

        // O += P @ V
#pragma unroll 8
        for (int mmi = 0; mmi < 64; mmi++) {
            float4 vv = *(const float4*)&Vs[mmi * TPITCH + c4 * 4];
            float p0 = Ps[(r4 * 4 + 0) * TPITCH + mmi];
            float p1 = Ps[(r4 * 4 + 1) * TPITCH + mmi];
            float p2 = Ps[(r4 * 4 + 2) * TPITCH + mmi];
            float p3 = Ps[(r4 * 4 + 3) * TPITCH + mmi];
            O[0][0] += p0 * vv.x; O[0][1] += p0 * vv.y; O[0][2] += p0 * vv.z; O[0][3] += p0 * vv.w;
            O[1][0] += p1 * vv.x; O[1][1] += p1 * vv.y; O[1][2] += p1 * vv.z; O[1][3] += p1 * vv.w;
            O[2][0] += p2 * vv.x; O[2][1] += p2 * vv.y; O[2][2] += p2 * vv.z; O[2][3] += p2 * vv.w;
            O[3][0] += p3 * vv.x; O[3][1] += p3 * vv.y; O[3][2] += p3 * vv.z; O[3][3] += p3 * vv.w;
        }
    }

    // normalize + write ctx in [B, N, H*Dh]
    float* outp = ctx + ((size_t)(b * NN + qi0)) * CC + h * DH;
#pragma unroll
    for (int i = 0; i < 4; i++) {
        const float inv = 1.0f / l_i[i];
        float4 o = make_float4(O[i][0] * inv, O[i][1] * inv,
                               O[i][2] * inv, O[i][3] * inv);
        *(float4*)&outp[(size_t)(r4 * 4 + i) * CC + c4 * 4] = o;
    }
}

// ---------------------------------------------------------------------------
extern "C" void kernel_launch(void* const* d_in, const int* in_sizes, int n_in,
                              void* d_out, int out_size)
{
    (void)in_sizes; (void)n_in; (void)out_size;
    const float* x     = (const float*)d_in[0];
    const float* Wq    = (const float*)d_in[1];
    const float* Wk    = (const float*)d_in[2];
    const float* Wv    = (const float*)d_in[3];
    const float* Wproj = (const float*)d_in[4];
    const float* bproj = (const float*)d_in[5];
    const float* Wpre  = (const float*)d_in[6];
    const float* bpre  = (const float*)d_in[7];
    const float* pi    = (const float*)d_in[8];
    float* out = (float*)d_out;

    float *pre, *qp, *kp, *vp, *lgp, *ctxp;
    cudaGetSymbolAddress((void**)&pre,  g_pre);
    cudaGetSymbolAddress((void**)&qp,   g_q);
    cudaGetSymbolAddress((void**)&kp,   g_k);
    cudaGetSymbolAddress((void**)&vp,   g_v);
    cudaGetSymbolAddress((void**)&lgp,  g_logits);
    cudaGetSymbolAddress((void**)&ctxp, g_ctx);

    dim3 blk(256);
    dim3 gl(CC / 64, MROWS / 64);            // (16, 64)

    gemm64<<<gl, blk>>>(x, Wpre, bpre, nullptr, pre,  CC, MODE_SILU);
    gemm64<<<gl, blk>>>(x, Wq,   nullptr, nullptr, qp, CC, MODE_BHND);
    gemm64<<<gl, blk>>>(x, Wk,   nullptr, nullptr, kp, CC, MODE_BHND);
    gemm64<<<gl, blk>>>(x, Wv,   nullptr, nullptr, vp, CC, MODE_BHND);

    dim3 glog(NN / 64, NN / 64, BB);         // (16, 16, 4)
    logits_k<<<glog, blk>>>(pre, lgp);

    cudaFuncSetAttribute(attn_k, cudaFuncAttributeMaxDynamicSharedMemorySize, SMEM_ATTN);
    dim3 ga(NN / 64, BB * HH);               // (16, 64)
    attn_k<<<ga, blk, SMEM_ATTN>>>(qp, kp, vp, lgp, pi, ctxp);

    gemm64<<<gl, blk>>>(ctxp, Wproj, bproj, x, out, CC, MODE_RESID);
}

// round 4
// speedup vs baseline: 1.7378x; 1.7378x over previous
#include <cuda_runtime.h>
#include <cuda_bf16.h>
#include <math.h>
#include <stdint.h>

#define BB 4
#define NN 1024
#define CC 1024
#define HH 16
#define DH 64
#define MROWS (BB*NN)   // 4096

// ---------------- scratch (device globals; no allocation allowed) ----------
__device__ float g_q[BB*HH*NN*DH];                 // 16 MB
__device__ float g_k[BB*HH*NN*DH];                 // 16 MB
__device__ float g_v[BB*HH*NN*DH];                 // 16 MB
__device__ float g_logits[BB*NN*NN];               // 16 MB
__device__ float g_ctx[MROWS*CC];                  // 16 MB
__device__ __nv_bfloat16 g_xh[MROWS*CC];           // 8 MB each
__device__ __nv_bfloat16 g_xl[MROWS*CC];
__device__ __nv_bfloat16 g_preh[MROWS*CC];
__device__ __nv_bfloat16 g_prel[MROWS*CC];
__device__ __nv_bfloat16 g_ctxh[MROWS*CC];
__device__ __nv_bfloat16 g_ctxl[MROWS*CC];
__device__ __nv_bfloat16 g_wpreh[CC*CC], g_wprel[CC*CC];
__device__ __nv_bfloat16 g_wqh[CC*CC],  g_wql[CC*CC];
__device__ __nv_bfloat16 g_wkh[CC*CC],  g_wkl[CC*CC];
__device__ __nv_bfloat16 g_wvh[CC*CC],  g_wvl[CC*CC];
__device__ __nv_bfloat16 g_wph[CC*CC],  g_wpl[CC*CC];

// ======================= portable PTX helpers (no sm_103a features) ========
__device__ __forceinline__ uint32_t smem_to_u32(const void* p) {
    uint32_t a;
    asm("{ .reg .u64 t; cvta.to.shared.u64 t, %1; cvt.u32.u64 %0, t; }"
        : "=r"(a) : "l"(p));
    return a;
}
#define CP_ASYNC16(dst, src) \
    asm volatile("cp.async.cg.shared.global [%0], [%1], 16;" \
                 :: "r"(dst), "l"(src) : "memory")
#define CP_COMMIT() asm volatile("cp.async.commit_group;" ::: "memory")
#define CP_WAIT1()  asm volatile("cp.async.wait_group 1;" ::: "memory")
#define CP_WAIT0()  asm volatile("cp.async.wait_group 0;" ::: "memory")

__device__ __forceinline__ void ldsm4(uint32_t* r, uint32_t addr) {
    asm volatile("ldmatrix.sync.aligned.m8n8.x4.shared.b16 {%0,%1,%2,%3}, [%4];"
        : "=r"(r[0]), "=r"(r[1]), "=r"(r[2]), "=r"(r[3]) : "r"(addr));
}
__device__ __forceinline__ void mma16816(float* c, const uint32_t* a,
                                         const uint32_t* b) {
    asm volatile("mma.sync.aligned.m16n8k16.row.col.f32.bf16.bf16.f32 "
        "{%0,%1,%2,%3}, {%4,%5,%6,%7}, {%8,%9}, {%0,%1,%2,%3};"
        : "+f"(c[0]), "+f"(c[1]), "+f"(c[2]), "+f"(c[3])
        : "r"(a[0]), "r"(a[1]), "r"(a[2]), "r"(a[3]), "r"(b[0]), "r"(b[1]));
}

// ======================= prep kernels ======================================
__global__ __launch_bounds__(256) void split2(
    const float2* __restrict__ in, __nv_bfloat162* __restrict__ hi,
    __nv_bfloat162* __restrict__ lo, int n2)
{
    int i = blockIdx.x * blockDim.x + threadIdx.x;
    if (i < n2) {
        float2 a = in[i];
        __nv_bfloat16 hx = __float2bfloat16(a.x), hy = __float2bfloat16(a.y);
        float lx = a.x - __bfloat162float(hx), ly = a.y - __bfloat162float(hy);
        hi[i] = __halves2bfloat162(hx, hy);
        lo[i] = __halves2bfloat162(__float2bfloat16(lx), __float2bfloat16(ly));
    }
}

// W[K,C] fp32 -> Wt_hi/lo[C,K] bf16 (transpose + split)
__global__ __launch_bounds__(256) void wsplit_T(
    const float* __restrict__ W, __nv_bfloat16* __restrict__ th,
    __nv_bfloat16* __restrict__ tl)
{
    __shared__ float s[32][33];
    const int tx = threadIdx.x, ty = threadIdx.y;
    const int n0 = blockIdx.x * 32, k0 = blockIdx.y * 32;
#pragma unroll
    for (int i = ty; i < 32; i += 8)
        s[i][tx] = W[(size_t)(k0 + i) * CC + n0 + tx];  // s[k][n]
    __syncthreads();
#pragma unroll
    for (int i = ty; i < 32; i += 8) {
        float v = s[tx][i];                              // W[k0+tx][n0+i]
        __nv_bfloat16 h = __float2bfloat16(v);
        float l = v - __bfloat162float(h);
        size_t o = (size_t)(n0 + i) * CC + k0 + tx;
        th[o] = h; tl[o] = __float2bfloat16(l);
    }
}

// ======================= HMMA GEMM (mma.sync bf16, 3-term split) ===========
// C[128x128 tile] = (Ah+Al)[M,K] . (Bh+Bl)[Ncols,K]^T, fp32 accumulate.
// 256 thr = 8 warps (2x4), warp tile 64x32. K-chunk 32, cp.async 2-stage.
// smem per stage: AH|AL|BH|BL, each 128 rows x 64B, XOR-16B swizzled.
enum { EPI_PRE = 0, EPI_BHND = 1, EPI_LOGITS = 2, EPI_RESID = 3 };

#define OFF_AH 0
#define OFF_AL 8192
#define OFF_BH 16384
#define OFF_BL 24576
#define STAGE_BYTES 32768
#define SMEM_HMMA (2 * STAGE_BYTES)    // 65536

__global__ __launch_bounds__(256) void hmma_gemm(
    const __nv_bfloat16* __restrict__ Ah, const __nv_bfloat16* __restrict__ Al,
    const __nv_bfloat16* __restrict__ Bh, const __nv_bfloat16* __restrict__ Bl,
    const float* __restrict__ bias, const float* __restrict__ resid,
    float* __restrict__ outF, __nv_bfloat16* __restrict__ outH,
    __nv_bfloat16* __restrict__ outL,
    int mode, long long bsA, long long bsB)
{
    extern __shared__ char smem_raw[];
    const uint32_t smem_u32 = smem_to_u32(smem_raw);
    const int t    = threadIdx.x;
    const int lane = t & 31;
    const int wid  = t >> 5;
    const int wr   = wid & 1;          // m half (64 rows)
    const int wc   = wid >> 1;         // n quarter (32 cols)
    const int row0 = blockIdx.y * 128;
    const int col0 = blockIdx.x * 128;
    const int z    = blockIdx.z;

    const __nv_bfloat16* Ahb = Ah + (size_t)z * bsA;
    const __nv_bfloat16* Alb = Al + (size_t)z * bsA;
    const __nv_bfloat16* Bhb = Bh + (size_t)z * bsB;
    const __nv_bfloat16* Blb = Bl + (size_t)z * bsB;

    // ---- loader map: thread t covers rows (t>>2)+{0,64}, 16B chunk c=t&3 ----
    const int lrow = t >> 2;
    const int lc   = t & 3;

    auto load_stage = [&](int ch, int s) {
        const size_t kb = (size_t)ch * 32 + lc * 8;        // gmem k element
        const uint32_t sb = smem_u32 + s * STAGE_BYTES;
#pragma unroll
        for (int i = 0; i < 2; i++) {
            const int r = lrow + i * 64;
            const uint32_t so = (uint32_t)(r * 64 + ((lc ^ (r & 3)) * 16));
            const size_t ga = (size_t)(row0 + r) * CC + kb;
            const size_t gb = (size_t)(col0 + r) * CC + kb;
            CP_ASYNC16(sb + OFF_AH + so, Ahb + ga);
            CP_ASYNC16(sb + OFF_AL + so, Alb + ga);
            CP_ASYNC16(sb + OFF_BH + so, Bhb + gb);
            CP_ASYNC16(sb + OFF_BL + so, Blb + gb);
        }
    };

    // ---- ldmatrix address components ----
    const int rowSel = lane & 15;       // row within 16-row ldmatrix group
    const int hiH    = lane >> 4;       // 0/1: k half
    const int rmod   = rowSel & 3;      // swizzle key

    float acc[4][4][4];
#pragma unroll
    for (int a = 0; a < 4; a++)
#pragma unroll
        for (int b = 0; b < 4; b++)
#pragma unroll
            for (int cjk = 0; cjk < 4; cjk++) acc[a][b][cjk] = 0.0f;

    load_stage(0, 0);
    CP_COMMIT();

    for (int ch = 0; ch < 32; ch++) {
        if (ch < 31) { load_stage(ch + 1, (ch + 1) & 1); CP_COMMIT(); CP_WAIT1(); }
        else CP_WAIT0();
        __syncthreads();

        const uint32_t sb = smem_u32 + (ch & 1) * STAGE_BYTES;
#pragma unroll
        for (int k16 = 0; k16 < 2; k16++) {
            const int chunk = k16 * 2 + hiH;
            uint32_t ah[4][4], al[4][4];
#pragma unroll
            for (int mt = 0; mt < 4; mt++) {
                const int row = wr * 64 + mt * 16 + rowSel;
                const uint32_t off = (uint32_t)(row * 64 + ((chunk ^ rmod) * 16));
                ldsm4(ah[mt], sb + OFF_AH + off);
                ldsm4(al[mt], sb + OFF_AL + off);
            }
            uint32_t bh[4][2], bl[4][2];
#pragma unroll
            for (int n16 = 0; n16 < 2; n16++) {
                const int row = wc * 32 + n16 * 16 + rowSel;
                const uint32_t off = (uint32_t)(row * 64 + ((chunk ^ rmod) * 16));
                uint32_t rh[4], rl[4];
                ldsm4(rh, sb + OFF_BH + off);
                ldsm4(rl, sb + OFF_BL + off);
                bh[n16 * 2][0] = rh[0]; bh[n16 * 2 + 1][0] = rh[1];
                bh[n16 * 2][1] = rh[2]; bh[n16 * 2 + 1][1] = rh[3];
                bl[n16 * 2][0] = rl[0]; bl[n16 * 2 + 1][0] = rl[1];
                bl[n16 * 2][1] = rl[2]; bl[n16 * 2 + 1][1] = rl[3];
            }
#pragma unroll
            for (int mt = 0; mt < 4; mt++)
#pragma unroll
                for (int nt = 0; nt < 4; nt++) {
                    mma16816(acc[mt][nt], ah[mt], bh[nt]);
                    mma16816(acc[mt][nt], ah[mt], bl[nt]);
                    mma16816(acc[mt][nt], al[mt], bh[nt]);
                }
        }
        __syncthreads();
    }

    // ---- epilogue: pairs (c0,c1)@(gr0,gc), (c2,c3)@(gr0+8,gc) ----
    const int r0g = row0 + wr * 64 + (lane >> 2);
    const int c0g = col0 + wc * 32 + (lane & 3) * 2;
#pragma unroll
    for (int mt = 0; mt < 4; mt++) {
#pragma unroll
        for (int nt = 0; nt < 4; nt++) {
            const int gc = c0g + nt * 8;
#pragma unroll
            for (int half = 0; half < 2; half++) {
                const int gr = r0g + mt * 16 + half * 8;
                float v0 = acc[mt][nt][half * 2 + 0];
                float v1 = acc[mt][nt][half * 2 + 1];
                if (mode == EPI_PRE) {
                    v0 += bias[gc]; v1 += bias[gc + 1];
                    v0 = v0 / (1.0f + __expf(-v0));
                    v1 = v1 / (1.0f + __expf(-v1));
                    __nv_bfloat16 h0 = __float2bfloat16(v0);
                    __nv_bfloat16 h1 = __float2bfloat16(v1);
                    const size_t ro = (size_t)gr * CC + gc;
                    *(__nv_bfloat162*)(outH + ro) = __halves2bfloat162(h0, h1);
                    *(__nv_bfloat162*)(outL + ro) = __halves2bfloat162(
                        __float2bfloat16(v0 - __bfloat162float(h0)),
                        __float2bfloat16(v1 - __bfloat162float(h1)));
                } else if (mode == EPI_BHND) {
                    const int b = gr >> 10, n = gr & (NN - 1);
                    const int h = gc >> 6, dh = gc & 63;
                    float* op = outF + (((size_t)(b * HH + h) * NN + n) * DH + dh);
                    op[0] = v0; op[1] = v1;
                } else if (mode == EPI_LOGITS) {
                    float* op = outF + (size_t)z * NN * NN + (size_t)gr * NN + gc;
                    op[0] = v0 * 0.03125f; op[1] = v1 * 0.03125f;
                } else { // EPI_RESID
                    const size_t ro = (size_t)gr * CC + gc;
                    outF[ro]     = v0 + bias[gc]     + resid[ro];
                    outF[ro + 1] = v1 + bias[gc + 1] + resid[ro + 1];
                }
            }
        }
    }
}

// ======================= flash attention (unchanged, passing) ==============
#define TPITCH 68
#define SMEM_ATTN (4 * 64 * TPITCH * (int)sizeof(float))

__global__ __launch_bounds__(256) void attn_k(
    const float* __restrict__ q, const float* __restrict__ k,
    const float* __restrict__ v, const float* __restrict__ logits,
    const float* __restrict__ pi_p, float* __restrict__ ctx)
{
    extern __shared__ float sm[];
    float* Qt = sm;
    float* Kt = sm + 64 * TPITCH;
    float* Vs = sm + 2 * 64 * TPITCH;
    float* Ps = sm + 3 * 64 * TPITCH;

    const int t  = threadIdx.x;
    const int r4 = t >> 4, c4 = t & 15;
    const int bh = blockIdx.y;
    const int b  = bh >> 4;
    const int h  = bh & 15;
    const int qi0 = blockIdx.x * 64;

    const float* qb = q + (size_t)bh * NN * DH;
    const float* kb = k + (size_t)bh * NN * DH;
    const float* vb = v + (size_t)bh * NN * DH;
    const float* lg = logits + (size_t)b * NN * NN + (size_t)qi0 * NN;
    const float pi = pi_p[0];

    const int lr  = t >> 2;
    const int ld0 = (t & 3) * 16;

    {
#pragma unroll
        for (int c = 0; c < 4; c++) {
            const int d = ld0 + c * 4;
            float4 qv = *(const float4*)&qb[(size_t)(qi0 + lr) * DH + d];
            Qt[(d + 0) * TPITCH + lr] = qv.x; Qt[(d + 1) * TPITCH + lr] = qv.y;
            Qt[(d + 2) * TPITCH + lr] = qv.z; Qt[(d + 3) * TPITCH + lr] = qv.w;
        }
    }

    float m_i[4], l_i[4], O[4][4];
#pragma unroll
    for (int i = 0; i < 4; i++) {
        m_i[i] = -1e30f; l_i[i] = 0.0f;
#pragma unroll
        for (int j = 0; j < 4; j++) O[i][j] = 0.0f;
    }

    for (int kt = 0; kt < 16; kt++) {
        const int mm0 = kt * 64;
        __syncthreads();
        {
#pragma unroll
            for (int c = 0; c < 4; c++) {
                const int d = ld0 + c * 4;
                float4 kv = *(const float4*)&kb[(size_t)(mm0 + lr) * DH + d];
                Kt[(d + 0) * TPITCH + lr] = kv.x; Kt[(d + 1) * TPITCH + lr] = kv.y;
                Kt[(d + 2) * TPITCH + lr] = kv.z; Kt[(d + 3) * TPITCH + lr] = kv.w;
                *(float4*)&Vs[lr * TPITCH + d] =
                    *(const float4*)&vb[(size_t)(mm0 + lr) * DH + d];
            }
        }
        __syncthreads();

        float s[4][4] = {};
#pragma unroll 8
        for (int d = 0; d < 64; d++) {
            float4 a = *(const float4*)&Qt[d * TPITCH + r4 * 4];
            float4 c = *(const float4*)&Kt[d * TPITCH + c4 * 4];
            float ar[4] = {a.x, a.y, a.z, a.w};
            float br[4] = {c.x, c.y, c.z, c.w};
#pragma unroll
            for (int i = 0; i < 4; i++)
#pragma unroll
                for (int j = 0; j < 4; j++)
                    s[i][j] += ar[i] * br[j];
        }

#pragma unroll
        for (int i = 0; i < 4; i++) {
            float4 Lr = *(const float4*)&lg[(size_t)(r4 * 4 + i) * NN + mm0 + c4 * 4];
            s[i][0] = s[i][0] * 0.125f + pi * Lr.x;
            s[i][1] = s[i][1] * 0.125f + pi * Lr.y;
            s[i][2] = s[i][2] * 0.125f + pi * Lr.z;
            s[i][3] = s[i][3] * 0.125f + pi * Lr.w;

            float tm = fmaxf(fmaxf(s[i][0], s[i][1]), fmaxf(s[i][2], s[i][3]));
            tm = fmaxf(tm, __shfl_xor_sync(0xffffffffu, tm, 1));
            tm = fmaxf(tm, __shfl_xor_sync(0xffffffffu, tm, 2));
            tm = fmaxf(tm, __shfl_xor_sync(0xffffffffu, tm, 4));
            tm = fmaxf(tm, __shfl_xor_sync(0xffffffffu, tm, 8));
            const float mn   = fmaxf(m_i[i], tm);
            const float alpha = __expf(m_i[i] - mn);
            m_i[i] = mn;

            float ps = 0.0f;
#pragma unroll
            for (int j = 0; j < 4; j++) {
                s[i][j] = __expf(s[i][j] - mn);
                ps += s[i][j];
            }
            ps += __shfl_xor_sync(0xffffffffu, ps, 1);
            ps += __shfl_xor_sync(0xffffffffu, ps, 2);
            ps += __shfl_xor_sync(0xffffffffu, ps, 4);
            ps += __shfl_xor_sync(0xffffffffu, ps, 8);
            l_i[i] = l_i[i] * alpha + ps;
#pragma unroll
            for (int j = 0; j < 4; j++) O[i][j] *= alpha;

            *(float4*)&Ps[(r4 * 4 + i) * TPITCH + c4 * 4] =
                make_float4(s[i][0], s[i][1], s[i][2], s[i][3]);
        }
        __syncthreads();

#pragma unroll 8
        for (int mmi = 0; mmi < 64; mmi++) {
            float4 vv = *(const float4*)&Vs[mmi * TPITCH + c4 * 4];
            float p0 = Ps[(r4 * 4 + 0) * TPITCH + mmi];
            float p1 = Ps[(r4 * 4 + 1) * TPITCH + mmi];
            float p2 = Ps[(r4 * 4 + 2) * TPITCH + mmi];
            float p3 = Ps[(r4 * 4 + 3) * TPITCH + mmi];
            O[0][0] += p0 * vv.x; O[0][1] += p0 * vv.y; O[0][2] += p0 * vv.z; O[0][3] += p0 * vv.w;
            O[1][0] += p1 * vv.x; O[1][1] += p1 * vv.y; O[1][2] += p1 * vv.z; O[1][3] += p1 * vv.w;
            O[2][0] += p2 * vv.x; O[2][1] += p2 * vv.y; O[2][2] += p2 * vv.z; O[2][3] += p2 * vv.w;
            O[3][0] += p3 * vv.x; O[3][1] += p3 * vv.y; O[3][2] += p3 * vv.z; O[3][3] += p3 * vv.w;
        }
    }

    float* outp = ctx + ((size_t)(b * NN + qi0)) * CC + h * DH;
#pragma unroll
    for (int i = 0; i < 4; i++) {
        const float inv = 1.0f / l_i[i];
        float4 o = make_float4(O[i][0] * inv, O[i][1] * inv,
                               O[i][2] * inv, O[i][3] * inv);
        *(float4*)&outp[(size_t)(r4 * 4 + i) * CC + c4 * 4] = o;
    }
}

// ---------------------------------------------------------------------------
extern "C" void kernel_launch(void* const* d_in, const int* in_sizes, int n_in,
                              void* d_out, int out_size)
{
    (void)in_sizes; (void)n_in; (void)out_size;
    const float* x     = (const float*)d_in[0];
    const float* Wq    = (const float*)d_in[1];
    const float* Wk    = (const float*)d_in[2];
    const float* Wv    = (const float*)d_in[3];
    const float* Wproj = (const float*)d_in[4];
    const float* bproj = (const float*)d_in[5];
    const float* Wpre  = (const float*)d_in[6];
    const float* bpre  = (const float*)d_in[7];
    const float* pi    = (const float*)d_in[8];
    float* out = (float*)d_out;

    float *qp, *kp, *vp, *lgp, *ctxp;
    __nv_bfloat16 *xh, *xl, *preh, *prel, *ctxh, *ctxl;
    __nv_bfloat16 *wpreh, *wprel, *wqh, *wql, *wkh, *wkl, *wvh, *wvl, *wph, *wpl;
    cudaGetSymbolAddress((void**)&qp,    g_q);
    cudaGetSymbolAddress((void**)&kp,    g_k);
    cudaGetSymbolAddress((void**)&vp,    g_v);
    cudaGetSymbolAddress((void**)&lgp,   g_logits);
    cudaGetSymbolAddress((void**)&ctxp,  g_ctx);
    cudaGetSymbolAddress((void**)&xh,    g_xh);
    cudaGetSymbolAddress((void**)&xl,    g_xl);
    cudaGetSymbolAddress((void**)&preh,  g_preh);
    cudaGetSymbolAddress((void**)&prel,  g_prel);
    cudaGetSymbolAddress((void**)&ctxh,  g_ctxh);
    cudaGetSymbolAddress((void**)&ctxl,  g_ctxl);
    cudaGetSymbolAddress((void**)&wpreh, g_wpreh);
    cudaGetSymbolAddress((void**)&wprel, g_wprel);
    cudaGetSymbolAddress((void**)&wqh,   g_wqh);
    cudaGetSymbolAddress((void**)&wql,   g_wql);
    cudaGetSymbolAddress((void**)&wkh,   g_wkh);
    cudaGetSymbolAddress((void**)&wkl,   g_wkl);
    cudaGetSymbolAddress((void**)&wvh,   g_wvh);
    cudaGetSymbolAddress((void**)&wvl,   g_wvl);
    cudaGetSymbolAddress((void**)&wph,   g_wph);
    cudaGetSymbolAddress((void**)&wpl,   g_wpl);

    cudaFuncSetAttribute(hmma_gemm, cudaFuncAttributeMaxDynamicSharedMemorySize, SMEM_HMMA);
    cudaFuncSetAttribute(attn_k,    cudaFuncAttributeMaxDynamicSharedMemorySize, SMEM_ATTN);

    // ---- prep: weight transpose+split, x split ----
    dim3 wst(32, 8), wsg(32, 32);
    wsplit_T<<<wsg, wst>>>(Wpre,  wpreh, wprel);
    wsplit_T<<<wsg, wst>>>(Wq,    wqh,   wql);
    wsplit_T<<<wsg, wst>>>(Wk,    wkh,   wkl);
    wsplit_T<<<wsg, wst>>>(Wv,    wvh,   wvl);
    wsplit_T<<<wsg, wst>>>(Wproj, wph,   wpl);
    const int n2 = MROWS * CC / 2;
    split2<<<(n2 + 255) / 256, 256>>>((const float2*)x,
        (__nv_bfloat162*)xh, (__nv_bfloat162*)xl, n2);

    // ---- tensor-core GEMMs (HMMA mma.sync) ----
    dim3 mb(256);
    dim3 gl(CC / 128, MROWS / 128, 1);           // (8, 32)
    hmma_gemm<<<gl, mb, SMEM_HMMA>>>(xh, xl, wpreh, wprel, bpre, nullptr,
                                     nullptr, preh, prel, EPI_PRE, 0, 0);
    hmma_gemm<<<gl, mb, SMEM_HMMA>>>(xh, xl, wqh, wql, nullptr, nullptr,
                                     qp, nullptr, nullptr, EPI_BHND, 0, 0);
    hmma_gemm<<<gl, mb, SMEM_HMMA>>>(xh, xl, wkh, wkl, nullptr, nullptr,
                                     kp, nullptr, nullptr, EPI_BHND, 0, 0);
    hmma_gemm<<<gl, mb, SMEM_HMMA>>>(xh, xl, wvh, wvl, nullptr, nullptr,
                                     vp, nullptr, nullptr, EPI_BHND, 0, 0);
    dim3 glog(NN / 128, NN / 128, BB);           // (8, 8, 4)
    hmma_gemm<<<glog, mb, SMEM_HMMA>>>(preh, prel, preh, prel, nullptr, nullptr,
                                       lgp, nullptr, nullptr, EPI_LOGITS,
                                       (long long)NN * CC, (long long)NN * CC);

    // ---- attention (fp32 SIMT flash) ----
    dim3 ga(NN / 64, BB * HH);
    attn_k<<<ga, 256, SMEM_ATTN>>>(qp, kp, vp, lgp, pi, ctxp);

    // ---- projection + residual ----
    split2<<<(n2 + 255) / 256, 256>>>((const float2*)ctxp,
        (__nv_bfloat162*)ctxh, (__nv_bfloat162*)ctxl, n2);
    hmma_gemm<<<gl, mb, SMEM_HMMA>>>(ctxh, ctxl, wph, wpl, bproj, x,
                                     out, nullptr, nullptr, EPI_RESID, 0, 0);
}

// round 5
// speedup vs baseline: 2.5482x; 1.4663x over previous
#include <cuda_runtime.h>
#include <cuda_bf16.h>
#include <math.h>
#include <stdint.h>

#define BB 4
#define NN 1024
#define CC 1024
#define HH 16
#define DH 64
#define MROWS (BB*NN)   // 4096

// ---------------- scratch (device globals; no allocation allowed) ----------
__device__ float g_logits[BB*NN*NN];               // 16 MB
__device__ __nv_bfloat16 g_xh[MROWS*CC];           // 8 MB each
__device__ __nv_bfloat16 g_xl[MROWS*CC];
__device__ __nv_bfloat16 g_preh[MROWS*CC];
__device__ __nv_bfloat16 g_prel[MROWS*CC];
__device__ __nv_bfloat16 g_ctxh[MROWS*CC];
__device__ __nv_bfloat16 g_ctxl[MROWS*CC];
__device__ __nv_bfloat16 g_qh[BB*HH*NN*DH], g_ql[BB*HH*NN*DH];
__device__ __nv_bfloat16 g_kh[BB*HH*NN*DH], g_kl[BB*HH*NN*DH];
__device__ __nv_bfloat16 g_vh[BB*HH*NN*DH], g_vl[BB*HH*NN*DH];
__device__ __nv_bfloat16 g_wpreh[CC*CC], g_wprel[CC*CC];
__device__ __nv_bfloat16 g_wqh[CC*CC],  g_wql[CC*CC];
__device__ __nv_bfloat16 g_wkh[CC*CC],  g_wkl[CC*CC];
__device__ __nv_bfloat16 g_wvh[CC*CC],  g_wvl[CC*CC];
__device__ __nv_bfloat16 g_wph[CC*CC],  g_wpl[CC*CC];

// ======================= portable PTX helpers (no sm_103a features) ========
__device__ __forceinline__ uint32_t smem_to_u32(const void* p) {
    uint32_t a;
    asm("{ .reg .u64 t; cvta.to.shared.u64 t, %1; cvt.u32.u64 %0, t; }"
        : "=r"(a) : "l"(p));
    return a;
}
#define CP_ASYNC16(dst, src) \
    asm volatile("cp.async.cg.shared.global [%0], [%1], 16;" \
                 :: "r"(dst), "l"(src) : "memory")
#define CP_COMMIT() asm volatile("cp.async.commit_group;" ::: "memory")
#define CP_WAIT1()  asm volatile("cp.async.wait_group 1;" ::: "memory")
#define CP_WAIT0()  asm volatile("cp.async.wait_group 0;" ::: "memory")

__device__ __forceinline__ void ldsm4(uint32_t* r, uint32_t addr) {
    asm volatile("ldmatrix.sync.aligned.m8n8.x4.shared.b16 {%0,%1,%2,%3}, [%4];"
        : "=r"(r[0]), "=r"(r[1]), "=r"(r[2]), "=r"(r[3]) : "r"(addr));
}
__device__ __forceinline__ void ldsm4t(uint32_t* r, uint32_t addr) {
    asm volatile("ldmatrix.sync.aligned.m8n8.x4.trans.shared.b16 {%0,%1,%2,%3}, [%4];"
        : "=r"(r[0]), "=r"(r[1]), "=r"(r[2]), "=r"(r[3]) : "r"(addr));
}
__device__ __forceinline__ void mma16816(float* c, const uint32_t* a,
                                         const uint32_t* b) {
    asm volatile("mma.sync.aligned.m16n8k16.row.col.f32.bf16.bf16.f32 "
        "{%0,%1,%2,%3}, {%4,%5,%6,%7}, {%8,%9}, {%0,%1,%2,%3};"
        : "+f"(c[0]), "+f"(c[1]), "+f"(c[2]), "+f"(c[3])
        : "r"(a[0]), "r"(a[1]), "r"(a[2]), "r"(a[3]), "r"(b[0]), "r"(b[1]));
}
__device__ __forceinline__ uint32_t pack_bf16(float x, float y) {
    __nv_bfloat162 p = __halves2bfloat162(__float2bfloat16(x), __float2bfloat16(y));
    return *(uint32_t*)&p;
}

// ======================= prep kernels ======================================
__global__ __launch_bounds__(256) void split2(
    const float2* __restrict__ in, __nv_bfloat162* __restrict__ hi,
    __nv_bfloat162* __restrict__ lo, int n2)
{
    int i = blockIdx.x * blockDim.x + threadIdx.x;
    if (i < n2) {
        float2 a = in[i];
        __nv_bfloat16 hx = __float2bfloat16(a.x), hy = __float2bfloat16(a.y);
        float lx = a.x - __bfloat162float(hx), ly = a.y - __bfloat162float(hy);
        hi[i] = __halves2bfloat162(hx, hy);
        lo[i] = __halves2bfloat162(__float2bfloat16(lx), __float2bfloat16(ly));
    }
}

// W[K,C] fp32 -> Wt_hi/lo[C,K] bf16 (transpose + split)
__global__ __launch_bounds__(256) void wsplit_T(
    const float* __restrict__ W, __nv_bfloat16* __restrict__ th,
    __nv_bfloat16* __restrict__ tl)
{
    __shared__ float s[32][33];
    const int tx = threadIdx.x, ty = threadIdx.y;
    const int n0 = blockIdx.x * 32, k0 = blockIdx.y * 32;
#pragma unroll
    for (int i = ty; i < 32; i += 8)
        s[i][tx] = W[(size_t)(k0 + i) * CC + n0 + tx];
    __syncthreads();
#pragma unroll
    for (int i = ty; i < 32; i += 8) {
        float v = s[tx][i];
        __nv_bfloat16 h = __float2bfloat16(v);
        float l = v - __bfloat162float(h);
        size_t o = (size_t)(n0 + i) * CC + k0 + tx;
        th[o] = h; tl[o] = __float2bfloat16(l);
    }
}

// ======================= HMMA GEMM (mma.sync bf16, 3-term split) ===========
enum { EPI_PRE = 0, EPI_BHND = 1, EPI_LOGITS = 2, EPI_RESID = 3 };

#define OFF_AH 0
#define OFF_AL 8192
#define OFF_BH 16384
#define OFF_BL 24576
#define STAGE_BYTES 32768
#define SMEM_HMMA (2 * STAGE_BYTES)    // 65536

__global__ __launch_bounds__(256) void hmma_gemm(
    const __nv_bfloat16* __restrict__ Ah, const __nv_bfloat16* __restrict__ Al,
    const __nv_bfloat16* __restrict__ Bh, const __nv_bfloat16* __restrict__ Bl,
    const float* __restrict__ bias, const float* __restrict__ resid,
    float* __restrict__ outF, __nv_bfloat16* __restrict__ outH,
    __nv_bfloat16* __restrict__ outL,
    int mode, long long bsA, long long bsB)
{
    extern __shared__ char smem_raw[];
    const uint32_t smem_u32 = smem_to_u32(smem_raw);
    const int t    = threadIdx.x;
    const int lane = t & 31;
    const int wid  = t >> 5;
    const int wr   = wid & 1;
    const int wc   = wid >> 1;
    const int row0 = blockIdx.y * 128;
    const int col0 = blockIdx.x * 128;
    const int z    = blockIdx.z;

    const __nv_bfloat16* Ahb = Ah + (size_t)z * bsA;
    const __nv_bfloat16* Alb = Al + (size_t)z * bsA;
    const __nv_bfloat16* Bhb = Bh + (size_t)z * bsB;
    const __nv_bfloat16* Blb = Bl + (size_t)z * bsB;

    const int lrow = t >> 2;
    const int lc   = t & 3;

    auto load_stage = [&](int ch, int s) {
        const size_t kb = (size_t)ch * 32 + lc * 8;
        const uint32_t sb = smem_u32 + s * STAGE_BYTES;
#pragma unroll
        for (int i = 0; i < 2; i++) {
            const int r = lrow + i * 64;
            const uint32_t so = (uint32_t)(r * 64 + ((lc ^ (r & 3)) * 16));
            const size_t ga = (size_t)(row0 + r) * CC + kb;
            const size_t gb = (size_t)(col0 + r) * CC + kb;
            CP_ASYNC16(sb + OFF_AH + so, Ahb + ga);
            CP_ASYNC16(sb + OFF_AL + so, Alb + ga);
            CP_ASYNC16(sb + OFF_BH + so, Bhb + gb);
            CP_ASYNC16(sb + OFF_BL + so, Blb + gb);
        }
    };

    const int rowSel = lane & 15;
    const int hiH    = lane >> 4;
    const int rmod   = rowSel & 3;

    float acc[4][4][4];
#pragma unroll
    for (int a = 0; a < 4; a++)
#pragma unroll
        for (int b = 0; b < 4; b++)
#pragma unroll
            for (int cjk = 0; cjk < 4; cjk++) acc[a][b][cjk] = 0.0f;

    load_stage(0, 0);
    CP_COMMIT();

    for (int ch = 0; ch < 32; ch++) {
        if (ch < 31) { load_stage(ch + 1, (ch + 1) & 1); CP_COMMIT(); CP_WAIT1(); }
        else CP_WAIT0();
        __syncthreads();

        const uint32_t sb = smem_u32 + (ch & 1) * STAGE_BYTES;
#pragma unroll
        for (int k16 = 0; k16 < 2; k16++) {
            const int chunk = k16 * 2 + hiH;
            uint32_t ah[4][4], al[4][4];
#pragma unroll
            for (int mt = 0; mt < 4; mt++) {
                const int row = wr * 64 + mt * 16 + rowSel;
                const uint32_t off = (uint32_t)(row * 64 + ((chunk ^ rmod) * 16));
                ldsm4(ah[mt], sb + OFF_AH + off);
                ldsm4(al[mt], sb + OFF_AL + off);
            }
            uint32_t bh[4][2], bl[4][2];
#pragma unroll
            for (int n16 = 0; n16 < 2; n16++) {
                const int row = wc * 32 + n16 * 16 + rowSel;
                const uint32_t off = (uint32_t)(row * 64 + ((chunk ^ rmod) * 16));
                uint32_t rh[4], rl[4];
                ldsm4(rh, sb + OFF_BH + off);
                ldsm4(rl, sb + OFF_BL + off);
                bh[n16 * 2][0] = rh[0]; bh[n16 * 2 + 1][0] = rh[1];
                bh[n16 * 2][1] = rh[2]; bh[n16 * 2 + 1][1] = rh[3];
                bl[n16 * 2][0] = rl[0]; bl[n16 * 2 + 1][0] = rl[1];
                bl[n16 * 2][1] = rl[2]; bl[n16 * 2 + 1][1] = rl[3];
            }
#pragma unroll
            for (int mt = 0; mt < 4; mt++)
#pragma unroll
                for (int nt = 0; nt < 4; nt++) {
                    mma16816(acc[mt][nt], ah[mt], bh[nt]);
                    mma16816(acc[mt][nt], ah[mt], bl[nt]);
                    mma16816(acc[mt][nt], al[mt], bh[nt]);
                }
        }
        __syncthreads();
    }

    const int r0g = row0 + wr * 64 + (lane >> 2);
    const int c0g = col0 + wc * 32 + (lane & 3) * 2;
#pragma unroll
    for (int mt = 0; mt < 4; mt++) {
#pragma unroll
        for (int nt = 0; nt < 4; nt++) {
            const int gc = c0g + nt * 8;
#pragma unroll
            for (int half = 0; half < 2; half++) {
                const int gr = r0g + mt * 16 + half * 8;
                float v0 = acc[mt][nt][half * 2 + 0];
                float v1 = acc[mt][nt][half * 2 + 1];
                if (mode == EPI_PRE) {
                    v0 += bias[gc]; v1 += bias[gc + 1];
                    v0 = v0 / (1.0f + __expf(-v0));
                    v1 = v1 / (1.0f + __expf(-v1));
                    __nv_bfloat16 h0 = __float2bfloat16(v0);
                    __nv_bfloat16 h1 = __float2bfloat16(v1);
                    const size_t ro = (size_t)gr * CC + gc;
                    *(__nv_bfloat162*)(outH + ro) = __halves2bfloat162(h0, h1);
                    *(__nv_bfloat162*)(outL + ro) = __halves2bfloat162(
                        __float2bfloat16(v0 - __bfloat162float(h0)),
                        __float2bfloat16(v1 - __bfloat162float(h1)));
                } else if (mode == EPI_BHND) {
                    // bf16 hi/lo split scattered to [B*H][N][Dh]
                    const int b = gr >> 10, n = gr & (NN - 1);
                    const int h = gc >> 6, dh = gc & 63;
                    const size_t o = ((size_t)(b * HH + h) * NN + n) * DH + dh;
                    __nv_bfloat16 h0 = __float2bfloat16(v0);
                    __nv_bfloat16 h1 = __float2bfloat16(v1);
                    *(__nv_bfloat162*)(outH + o) = __halves2bfloat162(h0, h1);
                    *(__nv_bfloat162*)(outL + o) = __halves2bfloat162(
                        __float2bfloat16(v0 - __bfloat162float(h0)),
                        __float2bfloat16(v1 - __bfloat162float(h1)));
                } else if (mode == EPI_LOGITS) {
                    float* op = outF + (size_t)z * NN * NN + (size_t)gr * NN + gc;
                    op[0] = v0 * 0.03125f; op[1] = v1 * 0.03125f;
                } else { // EPI_RESID
                    const size_t ro = (size_t)gr * CC + gc;
                    outF[ro]     = v0 + bias[gc]     + resid[ro];
                    outF[ro + 1] = v1 + bias[gc + 1] + resid[ro + 1];
                }
            }
        }
    }
}

// ======================= HMMA flash attention ==============================
// CTA = 64 queries, 4 warps (16 q-rows each), loop 16 key-tiles of 64.
// S = Qh.Kh^T + Qh.Kl^T + Ql.Kh^T (fp32 accum); softmax in C-frag registers;
// P split hi/lo; O += Ph.Vh + Ph.Vl + Pl.Vh via ldmatrix.trans on V.
#define SMQ_H 0
#define SMQ_L 8192
#define SMK_H 16384
#define SMK_L 24576
#define SMV_H 32768
#define SMV_L 40960
#define SMEM_FATT 49152

__global__ __launch_bounds__(128, 3) void fattn(
    const __nv_bfloat16* __restrict__ qh, const __nv_bfloat16* __restrict__ ql,
    const __nv_bfloat16* __restrict__ kh, const __nv_bfloat16* __restrict__ kl,
    const __nv_bfloat16* __restrict__ vh, const __nv_bfloat16* __restrict__ vl,
    const float* __restrict__ logits, const float* __restrict__ pi_p,
    __nv_bfloat16* __restrict__ ctxh, __nv_bfloat16* __restrict__ ctxl)
{
    extern __shared__ char sm[];
    const uint32_t sb = smem_to_u32(sm);
    const int t = threadIdx.x, lane = t & 31, w = t >> 5;
    const int bh = blockIdx.y, b = bh >> 4, h = bh & 15;
    const int q0 = blockIdx.x * 64;
    const size_t hoff = (size_t)bh * NN * DH;
    const float pi = pi_p[0];

    // Q async load (once)
#pragma unroll
    for (int i = 0; i < 4; i++) {
        const int id = t + i * 128;
        const int r = id >> 3, c = id & 7;
        const uint32_t off = (uint32_t)(r * 128 + ((c ^ (r & 7)) * 16));
        const size_t g = hoff + (size_t)(q0 + r) * DH + c * 8;
        CP_ASYNC16(sb + SMQ_H + off, qh + g);
        CP_ASYNC16(sb + SMQ_L + off, ql + g);
    }
    CP_COMMIT();

    float S[8][4], O[8][4];
#pragma unroll
    for (int j = 0; j < 8; j++)
#pragma unroll
        for (int c = 0; c < 4; c++) O[j][c] = 0.0f;
    float m0 = -1e30f, m1 = -1e30f, l0 = 0.0f, l1 = 0.0f;

    const int qr = w * 16 + (lane >> 2);                 // frag row (local)
    const float* lgr = logits + (size_t)b * NN * NN + (size_t)(q0 + qr) * NN;
    const int rowSel = lane & 15, hiH = lane >> 4;

    for (int kt = 0; kt < 16; kt++) {
        const int mk = kt * 64;
        __syncthreads();           // prior compute done reading K/V smem
#pragma unroll
        for (int i = 0; i < 4; i++) {
            const int id = t + i * 128;
            const int r = id >> 3, c = id & 7;
            const uint32_t off = (uint32_t)(r * 128 + ((c ^ (r & 7)) * 16));
            const size_t g = hoff + (size_t)(mk + r) * DH + c * 8;
            CP_ASYNC16(sb + SMK_H + off, kh + g);
            CP_ASYNC16(sb + SMK_L + off, kl + g);
            CP_ASYNC16(sb + SMV_H + off, vh + g);
            CP_ASYNC16(sb + SMV_L + off, vl + g);
        }
        CP_COMMIT(); CP_WAIT0();
        __syncthreads();

        // ---- S = Q K^T (3-term) ----
#pragma unroll
        for (int j = 0; j < 8; j++)
#pragma unroll
            for (int c = 0; c < 4; c++) S[j][c] = 0.0f;

#pragma unroll
        for (int kc = 0; kc < 4; kc++) {
            const int chunk = 2 * kc + hiH;
            uint32_t aqh[4], aql[4];
            {
                const int row = w * 16 + rowSel;
                const uint32_t off = (uint32_t)(row * 128 + ((chunk ^ (row & 7)) * 16));
                ldsm4(aqh, sb + SMQ_H + off);
                ldsm4(aql, sb + SMQ_L + off);
            }
#pragma unroll
            for (int j16 = 0; j16 < 4; j16++) {
                const int row = j16 * 16 + rowSel;
                const uint32_t off = (uint32_t)(row * 128 + ((chunk ^ (row & 7)) * 16));
                uint32_t rh[4], rl[4];
                ldsm4(rh, sb + SMK_H + off);
                ldsm4(rl, sb + SMK_L + off);
                uint32_t b0h[2] = {rh[0], rh[2]}, b1h[2] = {rh[1], rh[3]};
                uint32_t b0l[2] = {rl[0], rl[2]}, b1l[2] = {rl[1], rl[3]};
                mma16816(S[2 * j16],     aqh, b0h);
                mma16816(S[2 * j16],     aqh, b0l);
                mma16816(S[2 * j16],     aql, b0h);
                mma16816(S[2 * j16 + 1], aqh, b1h);
                mma16816(S[2 * j16 + 1], aqh, b1l);
                mma16816(S[2 * j16 + 1], aql, b1h);
            }
        }

        // ---- bias + online softmax (rows qr, qr+8) ----
        float mx0 = -1e30f, mx1 = -1e30f;
#pragma unroll
        for (int j = 0; j < 8; j++) {
            const float2 L0 = *(const float2*)(lgr + mk + j * 8 + (lane & 3) * 2);
            const float2 L1 = *(const float2*)(lgr + 8 * NN + mk + j * 8 + (lane & 3) * 2);
            S[j][0] = S[j][0] * 0.125f + pi * L0.x;
            S[j][1] = S[j][1] * 0.125f + pi * L0.y;
            S[j][2] = S[j][2] * 0.125f + pi * L1.x;
            S[j][3] = S[j][3] * 0.125f + pi * L1.y;
            mx0 = fmaxf(mx0, fmaxf(S[j][0], S[j][1]));
            mx1 = fmaxf(mx1, fmaxf(S[j][2], S[j][3]));
        }
        mx0 = fmaxf(mx0, __shfl_xor_sync(0xffffffffu, mx0, 1));
        mx0 = fmaxf(mx0, __shfl_xor_sync(0xffffffffu, mx0, 2));
        mx1 = fmaxf(mx1, __shfl_xor_sync(0xffffffffu, mx1, 1));
        mx1 = fmaxf(mx1, __shfl_xor_sync(0xffffffffu, mx1, 2));
        const float mn0 = fmaxf(m0, mx0), mn1 = fmaxf(m1, mx1);
        const float a0 = __expf(m0 - mn0), a1 = __expf(m1 - mn1);
        m0 = mn0; m1 = mn1;
        float s0 = 0.0f, s1 = 0.0f;
#pragma unroll
        for (int j = 0; j < 8; j++) {
            S[j][0] = __expf(S[j][0] - mn0); S[j][1] = __expf(S[j][1] - mn0);
            S[j][2] = __expf(S[j][2] - mn1); S[j][3] = __expf(S[j][3] - mn1);
            s0 += S[j][0] + S[j][1];
            s1 += S[j][2] + S[j][3];
        }
        s0 += __shfl_xor_sync(0xffffffffu, s0, 1);
        s0 += __shfl_xor_sync(0xffffffffu, s0, 2);
        s1 += __shfl_xor_sync(0xffffffffu, s1, 1);
        s1 += __shfl_xor_sync(0xffffffffu, s1, 2);
        l0 = l0 * a0 + s0; l1 = l1 * a1 + s1;
#pragma unroll
        for (int j = 0; j < 8; j++) {
            O[j][0] *= a0; O[j][1] *= a0; O[j][2] *= a1; O[j][3] *= a1;
        }

        // ---- O += P V (3-term), P from S regs, V via ldmatrix.trans ----
#pragma unroll
        for (int kc = 0; kc < 4; kc++) {
            uint32_t ph[4], pl[4];
#pragma unroll
            for (int half = 0; half < 2; half++) {
                const int j = 2 * kc + half;
                float x0 = S[j][0], x1 = S[j][1], x2 = S[j][2], x3 = S[j][3];
                uint32_t hp = pack_bf16(x0, x1);
                uint32_t hq = pack_bf16(x2, x3);
                ph[half * 2 + 0] = hp;  // wrong slot order fixed below
                ph[half * 2 + 1] = hq;
                __nv_bfloat162 hp2 = *(__nv_bfloat162*)&hp;
                __nv_bfloat162 hq2 = *(__nv_bfloat162*)&hq;
                pl[half * 2 + 0] = pack_bf16(x0 - __bfloat162float(__low2bfloat16(hp2)),
                                             x1 - __bfloat162float(__high2bfloat16(hp2)));
                pl[half * 2 + 1] = pack_bf16(x2 - __bfloat162float(__low2bfloat16(hq2)),
                                             x3 - __bfloat162float(__high2bfloat16(hq2)));
            }
            // A-frag order: a0=(r,k0-7 lo)=S[2kc]c01, a1=(r+8)=S[2kc]c23,
            //               a2=(r,k8-15)=S[2kc+1]c01, a3=S[2kc+1]c23  -> already matches
#pragma unroll
            for (int jc = 0; jc < 4; jc++) {
                const int row = kc * 16 + rowSel;
                const int chunk = 2 * jc + hiH;
                const uint32_t off = (uint32_t)(row * 128 + ((chunk ^ (row & 7)) * 16));
                uint32_t rvh[4], rvl[4];
                ldsm4t(rvh, sb + SMV_H + off);
                ldsm4t(rvl, sb + SMV_L + off);
                uint32_t v0h[2] = {rvh[0], rvh[1]}, v1h[2] = {rvh[2], rvh[3]};
                uint32_t v0l[2] = {rvl[0], rvl[1]}, v1l[2] = {rvl[2], rvl[3]};
                mma16816(O[2 * jc],     ph, v0h);
                mma16816(O[2 * jc],     ph, v0l);
                mma16816(O[2 * jc],     pl, v0h);
                mma16816(O[2 * jc + 1], ph, v1h);
                mma16816(O[2 * jc + 1], ph, v1l);
                mma16816(O[2 * jc + 1], pl, v1h);
            }
        }
    }

    // ---- epilogue: normalize, split hi/lo, write ctx [B,N,C] ----
    const float inv0 = 1.0f / l0, inv1 = 1.0f / l1;
    const size_t r0o = (size_t)(b * NN + q0 + qr) * CC;
    const size_t r1o = r0o + (size_t)8 * CC;
    const int cb = h * DH + (lane & 3) * 2;
#pragma unroll
    for (int dj = 0; dj < 8; dj++) {
        const int col = cb + dj * 8;
        float v0 = O[dj][0] * inv0, v1 = O[dj][1] * inv0;
        float v2 = O[dj][2] * inv1, v3 = O[dj][3] * inv1;
        __nv_bfloat16 h0 = __float2bfloat16(v0), h1 = __float2bfloat16(v1);
        __nv_bfloat16 h2 = __float2bfloat16(v2), h3 = __float2bfloat16(v3);
        *(__nv_bfloat162*)(ctxh + r0o + col) = __halves2bfloat162(h0, h1);
        *(__nv_bfloat162*)(ctxl + r0o + col) = __halves2bfloat162(
            __float2bfloat16(v0 - __bfloat162float(h0)),
            __float2bfloat16(v1 - __bfloat162float(h1)));
        *(__nv_bfloat162*)(ctxh + r1o + col) = __halves2bfloat162(h2, h3);
        *(__nv_bfloat162*)(ctxl + r1o + col) = __halves2bfloat162(
            __float2bfloat16(v2 - __bfloat162float(h2)),
            __float2bfloat16(v3 - __bfloat162float(h3)));
    }
}

// ---------------------------------------------------------------------------
extern "C" void kernel_launch(void* const* d_in, const int* in_sizes, int n_in,
                              void* d_out, int out_size)
{
    (void)in_sizes; (void)n_in; (void)out_size;
    const float* x     = (const float*)d_in[0];
    const float* Wq    = (const float*)d_in[1];
    const float* Wk    = (const float*)d_in[2];
    const float* Wv    = (const float*)d_in[3];
    const float* Wproj = (const float*)d_in[4];
    const float* bproj = (const float*)d_in[5];
    const float* Wpre  = (const float*)d_in[6];
    const float* bpre  = (const float*)d_in[7];
    const float* pi    = (const float*)d_in[8];
    float* out = (float*)d_out;

    float* lgp;
    __nv_bfloat16 *xh, *xl, *preh, *prel, *ctxh, *ctxl;
    __nv_bfloat16 *qhp, *qlp, *khp, *klp, *vhp, *vlp;
    __nv_bfloat16 *wpreh, *wprel, *wqh, *wql, *wkh, *wkl, *wvh, *wvl, *wph, *wpl;
    cudaGetSymbolAddress((void**)&lgp,   g_logits);
    cudaGetSymbolAddress((void**)&xh,    g_xh);
    cudaGetSymbolAddress((void**)&xl,    g_xl);
    cudaGetSymbolAddress((void**)&preh,  g_preh);
    cudaGetSymbolAddress((void**)&prel,  g_prel);
    cudaGetSymbolAddress((void**)&ctxh,  g_ctxh);
    cudaGetSymbolAddress((void**)&ctxl,  g_ctxl);
    cudaGetSymbolAddress((void**)&qhp,   g_qh);
    cudaGetSymbolAddress((void**)&qlp,   g_ql);
    cudaGetSymbolAddress((void**)&khp,   g_kh);
    cudaGetSymbolAddress((void**)&klp,   g_kl);
    cudaGetSymbolAddress((void**)&vhp,   g_vh);
    cudaGetSymbolAddress((void**)&vlp,   g_vl);
    cudaGetSymbolAddress((void**)&wpreh, g_wpreh);
    cudaGetSymbolAddress((void**)&wprel, g_wprel);
    cudaGetSymbolAddress((void**)&wqh,   g_wqh);
    cudaGetSymbolAddress((void**)&wql,   g_wql);
    cudaGetSymbolAddress((void**)&wkh,   g_wkh);
    cudaGetSymbolAddress((void**)&wkl,   g_wkl);
    cudaGetSymbolAddress((void**)&wvh,   g_wvh);
    cudaGetSymbolAddress((void**)&wvl,   g_wvl);
    cudaGetSymbolAddress((void**)&wph,   g_wph);
    cudaGetSymbolAddress((void**)&wpl,   g_wpl);

    cudaFuncSetAttribute(hmma_gemm, cudaFuncAttributeMaxDynamicSharedMemorySize, SMEM_HMMA);
    cudaFuncSetAttribute(fattn,     cudaFuncAttributeMaxDynamicSharedMemorySize, SMEM_FATT);

    // ---- prep ----
    dim3 wst(32, 8), wsg(32, 32);
    wsplit_T<<<wsg, wst>>>(Wpre,  wpreh, wprel);
    wsplit_T<<<wsg, wst>>>(Wq,    wqh,   wql);
    wsplit_T<<<wsg, wst>>>(Wk,    wkh,   wkl);
    wsplit_T<<<wsg, wst>>>(Wv,    wvh,   wvl);
    wsplit_T<<<wsg, wst>>>(Wproj, wph,   wpl);
    const int n2 = MROWS * CC / 2;
    split2<<<(n2 + 255) / 256, 256>>>((const float2*)x,
        (__nv_bfloat162*)xh, (__nv_bfloat162*)xl, n2);

    // ---- GEMMs ----
    dim3 mb(256);
    dim3 gl(CC / 128, MROWS / 128, 1);
    hmma_gemm<<<gl, mb, SMEM_HMMA>>>(xh, xl, wpreh, wprel, bpre, nullptr,
                                     nullptr, preh, prel, EPI_PRE, 0, 0);
    hmma_gemm<<<gl, mb, SMEM_HMMA>>>(xh, xl, wqh, wql, nullptr, nullptr,
                                     nullptr, qhp, qlp, EPI_BHND, 0, 0);
    hmma_gemm<<<gl, mb, SMEM_HMMA>>>(xh, xl, wkh, wkl, nullptr, nullptr,
                                     nullptr, khp, klp, EPI_BHND, 0, 0);
    hmma_gemm<<<gl, mb, SMEM_HMMA>>>(xh, xl, wvh, wvl, nullptr, nullptr,
                                     nullptr, vhp, vlp, EPI_BHND, 0, 0);
    dim3 glog(NN / 128, NN / 128, BB);
    hmma_gemm<<<glog, mb, SMEM_HMMA>>>(preh, prel, preh, prel, nullptr, nullptr,
                                       lgp, nullptr, nullptr, EPI_LOGITS,
                                       (long long)NN * CC, (long long)NN * CC);

    // ---- HMMA flash attention ----
    dim3 ga(NN / 64, BB * HH);
    fattn<<<ga, 128, SMEM_FATT>>>(qhp, qlp, khp, klp, vhp, vlp, lgp, pi,
                                  ctxh, ctxl);

    // ---- projection + residual ----
    hmma_gemm<<<gl, mb, SMEM_HMMA>>>(ctxh, ctxl, wph, wpl, bproj, x,
                                     out, nullptr, nullptr, EPI_RESID, 0, 0);
}

// round 6
// speedup vs baseline: 2.7514x; 1.0797x over previous
#include <cuda_runtime.h>
#include <cuda_bf16.h>
#include <math.h>
#include <stdint.h>

#define BB 4
#define NN 1024
#define CC 1024
#define HH 16
#define DH 64
#define MROWS (BB*NN)   // 4096

// ---------------- scratch (device globals; no allocation allowed) ----------
__device__ float g_logits[BB*NN*NN];               // 16 MB
__device__ __nv_bfloat16 g_xh[MROWS*CC];
__device__ __nv_bfloat16 g_xl[MROWS*CC];
__device__ __nv_bfloat16 g_preh[MROWS*CC];
__device__ __nv_bfloat16 g_prel[MROWS*CC];
__device__ __nv_bfloat16 g_ctxh[MROWS*CC];
__device__ __nv_bfloat16 g_ctxl[MROWS*CC];
__device__ __nv_bfloat16 g_qh[BB*HH*NN*DH], g_ql[BB*HH*NN*DH];
__device__ __nv_bfloat16 g_kh[BB*HH*NN*DH], g_kl[BB*HH*NN*DH];
__device__ __nv_bfloat16 g_vh[BB*HH*NN*DH], g_vl[BB*HH*NN*DH];
__device__ __nv_bfloat16 g_wpreh[CC*CC], g_wprel[CC*CC];
__device__ __nv_bfloat16 g_wqh[CC*CC],  g_wql[CC*CC];
__device__ __nv_bfloat16 g_wkh[CC*CC],  g_wkl[CC*CC];
__device__ __nv_bfloat16 g_wvh[CC*CC],  g_wvl[CC*CC];
__device__ __nv_bfloat16 g_wph[CC*CC],  g_wpl[CC*CC];

// ======================= portable PTX helpers ==============================
__device__ __forceinline__ uint32_t smem_to_u32(const void* p) {
    uint32_t a;
    asm("{ .reg .u64 t; cvta.to.shared.u64 t, %1; cvt.u32.u64 %0, t; }"
        : "=r"(a) : "l"(p));
    return a;
}
#define CP_ASYNC16(dst, src) \
    asm volatile("cp.async.cg.shared.global [%0], [%1], 16;" \
                 :: "r"(dst), "l"(src) : "memory")
#define CP_COMMIT() asm volatile("cp.async.commit_group;" ::: "memory")
#define CP_WAIT1()  asm volatile("cp.async.wait_group 1;" ::: "memory")
#define CP_WAIT0()  asm volatile("cp.async.wait_group 0;" ::: "memory")

__device__ __forceinline__ void ldsm4(uint32_t* r, uint32_t addr) {
    asm volatile("ldmatrix.sync.aligned.m8n8.x4.shared.b16 {%0,%1,%2,%3}, [%4];"
        : "=r"(r[0]), "=r"(r[1]), "=r"(r[2]), "=r"(r[3]) : "r"(addr));
}
__device__ __forceinline__ void ldsm4t(uint32_t* r, uint32_t addr) {
    asm volatile("ldmatrix.sync.aligned.m8n8.x4.trans.shared.b16 {%0,%1,%2,%3}, [%4];"
        : "=r"(r[0]), "=r"(r[1]), "=r"(r[2]), "=r"(r[3]) : "r"(addr));
}
__device__ __forceinline__ void mma16816(float* c, const uint32_t* a,
                                         const uint32_t* b) {
    asm volatile("mma.sync.aligned.m16n8k16.row.col.f32.bf16.bf16.f32 "
        "{%0,%1,%2,%3}, {%4,%5,%6,%7}, {%8,%9}, {%0,%1,%2,%3};"
        : "+f"(c[0]), "+f"(c[1]), "+f"(c[2]), "+f"(c[3])
        : "r"(a[0]), "r"(a[1]), "r"(a[2]), "r"(a[3]), "r"(b[0]), "r"(b[1]));
}
__device__ __forceinline__ uint32_t pack_bf16(float x, float y) {
    __nv_bfloat162 p = __halves2bfloat162(__float2bfloat16(x), __float2bfloat16(y));
    return *(uint32_t*)&p;
}

// ======================= prep kernels ======================================
__global__ __launch_bounds__(256) void split2(
    const float2* __restrict__ in, __nv_bfloat162* __restrict__ hi,
    __nv_bfloat162* __restrict__ lo, int n2)
{
    int i = blockIdx.x * blockDim.x + threadIdx.x;
    if (i < n2) {
        float2 a = in[i];
        __nv_bfloat16 hx = __float2bfloat16(a.x), hy = __float2bfloat16(a.y);
        float lx = a.x - __bfloat162float(hx), ly = a.y - __bfloat162float(hy);
        hi[i] = __halves2bfloat162(hx, hy);
        lo[i] = __halves2bfloat162(__float2bfloat16(lx), __float2bfloat16(ly));
    }
}

// 5 weights: W[K,C] fp32 -> Wt_hi/lo[C,K] bf16, grid.z selects the weight.
__global__ __launch_bounds__(256) void wsplit_T5(
    const float* __restrict__ W0, const float* __restrict__ W1,
    const float* __restrict__ W2, const float* __restrict__ W3,
    const float* __restrict__ W4,
    __nv_bfloat16* o0h, __nv_bfloat16* o0l, __nv_bfloat16* o1h, __nv_bfloat16* o1l,
    __nv_bfloat16* o2h, __nv_bfloat16* o2l, __nv_bfloat16* o3h, __nv_bfloat16* o3l,
    __nv_bfloat16* o4h, __nv_bfloat16* o4l)
{
    const float* Ws[5] = {W0, W1, W2, W3, W4};
    __nv_bfloat16* Hs[5] = {o0h, o1h, o2h, o3h, o4h};
    __nv_bfloat16* Ls[5] = {o0l, o1l, o2l, o3l, o4l};
    const int z = blockIdx.z;
    const float* W = Ws[z];
    __nv_bfloat16* th = Hs[z];
    __nv_bfloat16* tl = Ls[z];

    __shared__ float s[32][33];
    const int tx = threadIdx.x, ty = threadIdx.y;
    const int n0 = blockIdx.x * 32, k0 = blockIdx.y * 32;
#pragma unroll
    for (int i = ty; i < 32; i += 8)
        s[i][tx] = W[(size_t)(k0 + i) * CC + n0 + tx];
    __syncthreads();
#pragma unroll
    for (int i = ty; i < 32; i += 8) {
        float v = s[tx][i];
        __nv_bfloat16 h = __float2bfloat16(v);
        float l = v - __bfloat162float(h);
        size_t o = (size_t)(n0 + i) * CC + k0 + tx;
        th[o] = h; tl[o] = __float2bfloat16(l);
    }
}

// ======================= HMMA GEMM common machinery ========================
enum { EPI_PRE = 0, EPI_BHND = 1, EPI_LOGITS = 2, EPI_RESID = 3 };

#define OFF_AH 0
#define OFF_AL 8192
#define OFF_BH 16384
#define OFF_BL 24576
#define STAGE_BYTES 32768
#define SMEM_HMMA (2 * STAGE_BYTES)    // 65536

// Shared mainloop: accumulates C(128x128) = 3-term split A.B^T over K=1024.
// acc layout: acc[mt][nt][4], warp (wr, wc), thread frag rows per mma.sync.
struct GemmCore {
    uint32_t smem_u32;
    int lane, wid, wr, wc, lrow, lc, rowSel, hiH, rmod;
    __device__ __forceinline__ void init(uint32_t smem, int t) {
        smem_u32 = smem;
        lane = t & 31; wid = t >> 5;
        wr = wid & 1; wc = wid >> 1;
        lrow = t >> 2; lc = t & 3;
        rowSel = lane & 15; hiH = lane >> 4; rmod = rowSel & 3;
    }
    __device__ __forceinline__ void load_stage(
        const __nv_bfloat16* Ahb, const __nv_bfloat16* Alb,
        const __nv_bfloat16* Bhb, const __nv_bfloat16* Blb,
        int row0, int col0, int ch, int s) const
    {
        const size_t kb = (size_t)ch * 32 + lc * 8;
        const uint32_t sb = smem_u32 + s * STAGE_BYTES;
#pragma unroll
        for (int i = 0; i < 2; i++) {
            const int r = lrow + i * 64;
            const uint32_t so = (uint32_t)(r * 64 + ((lc ^ (r & 3)) * 16));
            const size_t ga = (size_t)(row0 + r) * CC + kb;
            const size_t gb = (size_t)(col0 + r) * CC + kb;
            CP_ASYNC16(sb + OFF_AH + so, Ahb + ga);
            CP_ASYNC16(sb + OFF_AL + so, Alb + ga);
            CP_ASYNC16(sb + OFF_BH + so, Bhb + gb);
            CP_ASYNC16(sb + OFF_BL + so, Blb + gb);
        }
    }
    __device__ __forceinline__ void run(
        const __nv_bfloat16* Ahb, const __nv_bfloat16* Alb,
        const __nv_bfloat16* Bhb, const __nv_bfloat16* Blb,
        int row0, int col0, float acc[4][4][4]) const
    {
#pragma unroll
        for (int a = 0; a < 4; a++)
#pragma unroll
            for (int b = 0; b < 4; b++)
#pragma unroll
                for (int c = 0; c < 4; c++) acc[a][b][c] = 0.0f;

        load_stage(Ahb, Alb, Bhb, Blb, row0, col0, 0, 0);
        CP_COMMIT();
        for (int ch = 0; ch < 32; ch++) {
            if (ch < 31) {
                load_stage(Ahb, Alb, Bhb, Blb, row0, col0, ch + 1, (ch + 1) & 1);
                CP_COMMIT(); CP_WAIT1();
            } else CP_WAIT0();
            __syncthreads();

            const uint32_t sb = smem_u32 + (ch & 1) * STAGE_BYTES;
#pragma unroll
            for (int k16 = 0; k16 < 2; k16++) {
                const int chunk = k16 * 2 + hiH;
                uint32_t ah[4][4], al[4][4];
#pragma unroll
                for (int mt = 0; mt < 4; mt++) {
                    const int row = wr * 64 + mt * 16 + rowSel;
                    const uint32_t off = (uint32_t)(row * 64 + ((chunk ^ rmod) * 16));
                    ldsm4(ah[mt], sb + OFF_AH + off);
                    ldsm4(al[mt], sb + OFF_AL + off);
                }
                uint32_t bh[4][2], bl[4][2];
#pragma unroll
                for (int n16 = 0; n16 < 2; n16++) {
                    const int row = wc * 32 + n16 * 16 + rowSel;
                    const uint32_t off = (uint32_t)(row * 64 + ((chunk ^ rmod) * 16));
                    uint32_t rh[4], rl[4];
                    ldsm4(rh, sb + OFF_BH + off);
                    ldsm4(rl, sb + OFF_BL + off);
                    bh[n16 * 2][0] = rh[0]; bh[n16 * 2 + 1][0] = rh[1];
                    bh[n16 * 2][1] = rh[2]; bh[n16 * 2 + 1][1] = rh[3];
                    bl[n16 * 2][0] = rl[0]; bl[n16 * 2 + 1][0] = rl[1];
                    bl[n16 * 2][1] = rl[2]; bl[n16 * 2 + 1][1] = rl[3];
                }
#pragma unroll
                for (int mt = 0; mt < 4; mt++)
#pragma unroll
                    for (int nt = 0; nt < 4; nt++) {
                        mma16816(acc[mt][nt], ah[mt], bh[nt]);
                        mma16816(acc[mt][nt], ah[mt], bl[nt]);
                        mma16816(acc[mt][nt], al[mt], bh[nt]);
                    }
            }
            __syncthreads();
        }
    }
};

__device__ __forceinline__ void split_store(__nv_bfloat16* oh, __nv_bfloat16* ol,
                                            size_t off, float v0, float v1) {
    __nv_bfloat16 h0 = __float2bfloat16(v0);
    __nv_bfloat16 h1 = __float2bfloat16(v1);
    *(__nv_bfloat162*)(oh + off) = __halves2bfloat162(h0, h1);
    *(__nv_bfloat162*)(ol + off) = __halves2bfloat162(
        __float2bfloat16(v0 - __bfloat162float(h0)),
        __float2bfloat16(v1 - __bfloat162float(h1)));
}

// ---- merged pre/Q/K/V GEMM: grid (32, 32); group = blockIdx.x>>3 ----------
__global__ __launch_bounds__(256) void hmma_qkv(
    const __nv_bfloat16* __restrict__ xh, const __nv_bfloat16* __restrict__ xl,
    const __nv_bfloat16* wpreh, const __nv_bfloat16* wprel,
    const __nv_bfloat16* wqh, const __nv_bfloat16* wql,
    const __nv_bfloat16* wkh, const __nv_bfloat16* wkl,
    const __nv_bfloat16* wvh, const __nv_bfloat16* wvl,
    const float* __restrict__ bpre,
    __nv_bfloat16* preh, __nv_bfloat16* prel,
    __nv_bfloat16* qh, __nv_bfloat16* ql,
    __nv_bfloat16* kh, __nv_bfloat16* kl,
    __nv_bfloat16* vh, __nv_bfloat16* vl)
{
    extern __shared__ char smem_raw[];
    GemmCore gc_;
    gc_.init(smem_to_u32(smem_raw), threadIdx.x);

    const int g    = blockIdx.x >> 3;
    const int col0 = (blockIdx.x & 7) * 128;
    const int row0 = blockIdx.y * 128;

    const __nv_bfloat16* Bh[4] = {wpreh, wqh, wkh, wvh};
    const __nv_bfloat16* Bl[4] = {wprel, wql, wkl, wvl};
    __nv_bfloat16* OH[4] = {preh, qh, kh, vh};
    __nv_bfloat16* OL[4] = {prel, ql, kl, vl};

    float acc[4][4][4];
    gc_.run(xh, xl, Bh[g], Bl[g], row0, col0, acc);

    const int r0g = row0 + gc_.wr * 64 + (gc_.lane >> 2);
    const int c0g = col0 + gc_.wc * 32 + (gc_.lane & 3) * 2;
#pragma unroll
    for (int mt = 0; mt < 4; mt++) {
#pragma unroll
        for (int nt = 0; nt < 4; nt++) {
            const int gcc = c0g + nt * 8;
#pragma unroll
            for (int half = 0; half < 2; half++) {
                const int gr = r0g + mt * 16 + half * 8;
                float v0 = acc[mt][nt][half * 2 + 0];
                float v1 = acc[mt][nt][half * 2 + 1];
                if (g == 0) {
                    v0 += bpre[gcc]; v1 += bpre[gcc + 1];
                    v0 = v0 / (1.0f + __expf(-v0));
                    v1 = v1 / (1.0f + __expf(-v1));
                    split_store(OH[0], OL[0], (size_t)gr * CC + gcc, v0, v1);
                } else {
                    const int b = gr >> 10, n = gr & (NN - 1);
                    const int h = gcc >> 6, dh = gcc & 63;
                    const size_t o = ((size_t)(b * HH + h) * NN + n) * DH + dh;
                    split_store(OH[g], OL[g], o, v0, v1);
                }
            }
        }
    }
}

// ---- logits (symmetric, upper-tri tiles) + proj/resid GEMM ----------------
__global__ __launch_bounds__(256) void hmma_gemm(
    const __nv_bfloat16* __restrict__ Ah, const __nv_bfloat16* __restrict__ Al,
    const __nv_bfloat16* __restrict__ Bh, const __nv_bfloat16* __restrict__ Bl,
    const float* __restrict__ bias, const float* __restrict__ resid,
    float* __restrict__ outF, int mode, long long bsA, long long bsB)
{
    extern __shared__ char smem_raw[];
    GemmCore gc_;
    gc_.init(smem_to_u32(smem_raw), threadIdx.x);

    int row0, col0, ti = 0, tj = 0;
    if (mode == EPI_LOGITS) {
        int li = blockIdx.x, rem = 8;
        while (li >= rem) { li -= rem; rem--; ti++; }
        tj = ti + li;
        row0 = ti * 128; col0 = tj * 128;
    } else {
        row0 = blockIdx.y * 128;
        col0 = blockIdx.x * 128;
    }
    const int z = blockIdx.z;
    const __nv_bfloat16* Ahb = Ah + (size_t)z * bsA;
    const __nv_bfloat16* Alb = Al + (size_t)z * bsA;
    const __nv_bfloat16* Bhb = Bh + (size_t)z * bsB;
    const __nv_bfloat16* Blb = Bl + (size_t)z * bsB;

    float acc[4][4][4];
    gc_.run(Ahb, Alb, Bhb, Blb, row0, col0, acc);

    const int r0g = row0 + gc_.wr * 64 + (gc_.lane >> 2);
    const int c0g = col0 + gc_.wc * 32 + (gc_.lane & 3) * 2;
#pragma unroll
    for (int mt = 0; mt < 4; mt++) {
#pragma unroll
        for (int nt = 0; nt < 4; nt++) {
            const int gcc = c0g + nt * 8;
#pragma unroll
            for (int half = 0; half < 2; half++) {
                const int gr = r0g + mt * 16 + half * 8;
                float v0 = acc[mt][nt][half * 2 + 0];
                float v1 = acc[mt][nt][half * 2 + 1];
                if (mode == EPI_LOGITS) {
                    float* base = outF + (size_t)z * NN * NN;
                    v0 *= 0.03125f; v1 *= 0.03125f;
                    base[(size_t)gr * NN + gcc]     = v0;
                    base[(size_t)gr * NN + gcc + 1] = v1;
                    if (ti != tj) {
                        base[(size_t)gcc * NN + gr]       = v0;
                        base[(size_t)(gcc + 1) * NN + gr] = v1;
                    }
                } else { // EPI_RESID
                    const size_t ro = (size_t)gr * CC + gcc;
                    outF[ro]     = v0 + bias[gcc]     + resid[ro];
                    outF[ro + 1] = v1 + bias[gcc + 1] + resid[ro + 1];
                }
            }
        }
    }
}

// ======================= HMMA flash attention (128-q tile) =================
// CTA = 128 queries, 8 warps (16 q-rows each), loop 16 key-tiles of 64.
#define SMQ_H 0
#define SMQ_L 16384
#define SMK_H 32768
#define SMK_L 40960
#define SMV_H 49152
#define SMV_L 57344
#define SMEM_FATT 65536

__global__ __launch_bounds__(256, 2) void fattn(
    const __nv_bfloat16* __restrict__ qh, const __nv_bfloat16* __restrict__ ql,
    const __nv_bfloat16* __restrict__ kh, const __nv_bfloat16* __restrict__ kl,
    const __nv_bfloat16* __restrict__ vh, const __nv_bfloat16* __restrict__ vl,
    const float* __restrict__ logits, const float* __restrict__ pi_p,
    __nv_bfloat16* __restrict__ ctxh, __nv_bfloat16* __restrict__ ctxl)
{
    extern __shared__ char sm[];
    const uint32_t sb = smem_to_u32(sm);
    const int t = threadIdx.x, lane = t & 31, w = t >> 5;
    const int bh = blockIdx.y, b = bh >> 4, h = bh & 15;
    const int q0 = blockIdx.x * 128;
    const size_t hoff = (size_t)bh * NN * DH;
    const float pi = pi_p[0];

    // Q async load (once): 128 rows x 8 chunks per buffer
#pragma unroll
    for (int i = 0; i < 4; i++) {
        const int id = t + i * 256;
        const int r = id >> 3, c = id & 7;
        const uint32_t off = (uint32_t)(r * 128 + ((c ^ (r & 7)) * 16));
        const size_t g = hoff + (size_t)(q0 + r) * DH + c * 8;
        CP_ASYNC16(sb + SMQ_H + off, qh + g);
        CP_ASYNC16(sb + SMQ_L + off, ql + g);
    }
    CP_COMMIT();

    float S[8][4], O[8][4];
#pragma unroll
    for (int j = 0; j < 8; j++)
#pragma unroll
        for (int c = 0; c < 4; c++) O[j][c] = 0.0f;
    float m0 = -1e30f, m1 = -1e30f, l0 = 0.0f, l1 = 0.0f;

    const int qr = w * 16 + (lane >> 2);
    const float* lgr = logits + (size_t)b * NN * NN + (size_t)(q0 + qr) * NN;
    const int rowSel = lane & 15, hiH = lane >> 4;

    for (int kt = 0; kt < 16; kt++) {
        const int mk = kt * 64;
        __syncthreads();
#pragma unroll
        for (int i = 0; i < 2; i++) {
            const int id = t + i * 256;
            const int r = id >> 3, c = id & 7;
            const uint32_t off = (uint32_t)(r * 128 + ((c ^ (r & 7)) * 16));
            const size_t g = hoff + (size_t)(mk + r) * DH + c * 8;
            CP_ASYNC16(sb + SMK_H + off, kh + g);
            CP_ASYNC16(sb + SMK_L + off, kl + g);
            CP_ASYNC16(sb + SMV_H + off, vh + g);
            CP_ASYNC16(sb + SMV_L + off, vl + g);
        }
        CP_COMMIT(); CP_WAIT0();
        __syncthreads();

        // ---- S = Q K^T (3-term) ----
#pragma unroll
        for (int j = 0; j < 8; j++)
#pragma unroll
            for (int c = 0; c < 4; c++) S[j][c] = 0.0f;

#pragma unroll
        for (int kc = 0; kc < 4; kc++) {
            const int chunk = 2 * kc + hiH;
            uint32_t aqh[4], aql[4];
            {
                const int row = w * 16 + rowSel;
                const uint32_t off = (uint32_t)(row * 128 + ((chunk ^ (row & 7)) * 16));
                ldsm4(aqh, sb + SMQ_H + off);
                ldsm4(aql, sb + SMQ_L + off);
            }
#pragma unroll
            for (int j16 = 0; j16 < 4; j16++) {
                const int row = j16 * 16 + rowSel;
                const uint32_t off = (uint32_t)(row * 128 + ((chunk ^ (row & 7)) * 16));
                uint32_t rh[4], rl[4];
                ldsm4(rh, sb + SMK_H + off);
                ldsm4(rl, sb + SMK_L + off);
                uint32_t b0h[2] = {rh[0], rh[2]}, b1h[2] = {rh[1], rh[3]};
                uint32_t b0l[2] = {rl[0], rl[2]}, b1l[2] = {rl[1], rl[3]};
                mma16816(S[2 * j16],     aqh, b0h);
                mma16816(S[2 * j16],     aqh, b0l);
                mma16816(S[2 * j16],     aql, b0h);
                mma16816(S[2 * j16 + 1], aqh, b1h);
                mma16816(S[2 * j16 + 1], aqh, b1l);
                mma16816(S[2 * j16 + 1], aql, b1h);
            }
        }

        // ---- bias + online softmax ----
        float mx0 = -1e30f, mx1 = -1e30f;
#pragma unroll
        for (int j = 0; j < 8; j++) {
            const float2 L0 = *(const float2*)(lgr + mk + j * 8 + (lane & 3) * 2);
            const float2 L1 = *(const float2*)(lgr + 8 * NN + mk + j * 8 + (lane & 3) * 2);
            S[j][0] = S[j][0] * 0.125f + pi * L0.x;
            S[j][1] = S[j][1] * 0.125f + pi * L0.y;
            S[j][2] = S[j][2] * 0.125f + pi * L1.x;
            S[j][3] = S[j][3] * 0.125f + pi * L1.y;
            mx0 = fmaxf(mx0, fmaxf(S[j][0], S[j][1]));
            mx1 = fmaxf(mx1, fmaxf(S[j][2], S[j][3]));
        }
        mx0 = fmaxf(mx0, __shfl_xor_sync(0xffffffffu, mx0, 1));
        mx0 = fmaxf(mx0, __shfl_xor_sync(0xffffffffu, mx0, 2));
        mx1 = fmaxf(mx1, __shfl_xor_sync(0xffffffffu, mx1, 1));
        mx1 = fmaxf(mx1, __shfl_xor_sync(0xffffffffu, mx1, 2));
        const float mn0 = fmaxf(m0, mx0), mn1 = fmaxf(m1, mx1);
        const float a0 = __expf(m0 - mn0), a1 = __expf(m1 - mn1);
        m0 = mn0; m1 = mn1;
        float s0 = 0.0f, s1 = 0.0f;
#pragma unroll
        for (int j = 0; j < 8; j++) {
            S[j][0] = __expf(S[j][0] - mn0); S[j][1] = __expf(S[j][1] - mn0);
            S[j][2] = __expf(S[j][2] - mn1); S[j][3] = __expf(S[j][3] - mn1);
            s0 += S[j][0] + S[j][1];
            s1 += S[j][2] + S[j][3];
        }
        s0 += __shfl_xor_sync(0xffffffffu, s0, 1);
        s0 += __shfl_xor_sync(0xffffffffu, s0, 2);
        s1 += __shfl_xor_sync(0xffffffffu, s1, 1);
        s1 += __shfl_xor_sync(0xffffffffu, s1, 2);
        l0 = l0 * a0 + s0; l1 = l1 * a1 + s1;
#pragma unroll
        for (int j = 0; j < 8; j++) {
            O[j][0] *= a0; O[j][1] *= a0; O[j][2] *= a1; O[j][3] *= a1;
        }

        // ---- O += P V (3-term) ----
#pragma unroll
        for (int kc = 0; kc < 4; kc++) {
            uint32_t ph[4], pl[4];
#pragma unroll
            for (int half = 0; half < 2; half++) {
                const int j = 2 * kc + half;
                float x0 = S[j][0], x1 = S[j][1], x2 = S[j][2], x3 = S[j][3];
                uint32_t hp = pack_bf16(x0, x1);
                uint32_t hq = pack_bf16(x2, x3);
                ph[half * 2 + 0] = hp;
                ph[half * 2 + 1] = hq;
                __nv_bfloat162 hp2 = *(__nv_bfloat162*)&hp;
                __nv_bfloat162 hq2 = *(__nv_bfloat162*)&hq;
                pl[half * 2 + 0] = pack_bf16(x0 - __bfloat162float(__low2bfloat16(hp2)),
                                             x1 - __bfloat162float(__high2bfloat16(hp2)));
                pl[half * 2 + 1] = pack_bf16(x2 - __bfloat162float(__low2bfloat16(hq2)),
                                             x3 - __bfloat162float(__high2bfloat16(hq2)));
            }
#pragma unroll
            for (int jc = 0; jc < 4; jc++) {
                const int row = kc * 16 + rowSel;
                const int chunk = 2 * jc + hiH;
                const uint32_t off = (uint32_t)(row * 128 + ((chunk ^ (row & 7)) * 16));
                uint32_t rvh[4], rvl[4];
                ldsm4t(rvh, sb + SMV_H + off);
                ldsm4t(rvl, sb + SMV_L + off);
                uint32_t v0h[2] = {rvh[0], rvh[1]}, v1h[2] = {rvh[2], rvh[3]};
                uint32_t v0l[2] = {rvl[0], rvl[1]}, v1l[2] = {rvl[2], rvl[3]};
                mma16816(O[2 * jc],     ph, v0h);
                mma16816(O[2 * jc],     ph, v0l);
                mma16816(O[2 * jc],     pl, v0h);
                mma16816(O[2 * jc + 1], ph, v1h);
                mma16816(O[2 * jc + 1], ph, v1l);
                mma16816(O[2 * jc + 1], pl, v1h);
            }
        }
    }

    // ---- epilogue ----
    const float inv0 = 1.0f / l0, inv1 = 1.0f / l1;
    const size_t r0o = (size_t)(b * NN + q0 + qr) * CC;
    const size_t r1o = r0o + (size_t)8 * CC;
    const int cb = h * DH + (lane & 3) * 2;
#pragma unroll
    for (int dj = 0; dj < 8; dj++) {
        const int col = cb + dj * 8;
        split_store(ctxh, ctxl, r0o + col, O[dj][0] * inv0, O[dj][1] * inv0);
        split_store(ctxh, ctxl, r1o + col, O[dj][2] * inv1, O[dj][3] * inv1);
    }
}

// ---------------------------------------------------------------------------
extern "C" void kernel_launch(void* const* d_in, const int* in_sizes, int n_in,
                              void* d_out, int out_size)
{
    (void)in_sizes; (void)n_in; (void)out_size;
    const float* x     = (const float*)d_in[0];
    const float* Wq    = (const float*)d_in[1];
    const float* Wk    = (const float*)d_in[2];
    const float* Wv    = (const float*)d_in[3];
    const float* Wproj = (const float*)d_in[4];
    const float* bproj = (const float*)d_in[5];
    const float* Wpre  = (const float*)d_in[6];
    const float* bpre  = (const float*)d_in[7];
    const float* pi    = (const float*)d_in[8];
    float* out = (float*)d_out;

    float* lgp;
    __nv_bfloat16 *xh, *xl, *preh, *prel, *ctxh, *ctxl;
    __nv_bfloat16 *qhp, *qlp, *khp, *klp, *vhp, *vlp;
    __nv_bfloat16 *wpreh, *wprel, *wqh, *wql, *wkh, *wkl, *wvh, *wvl, *wph, *wpl;
    cudaGetSymbolAddress((void**)&lgp,   g_logits);
    cudaGetSymbolAddress((void**)&xh,    g_xh);
    cudaGetSymbolAddress((void**)&xl,    g_xl);
    cudaGetSymbolAddress((void**)&preh,  g_preh);
    cudaGetSymbolAddress((void**)&prel,  g_prel);
    cudaGetSymbolAddress((void**)&ctxh,  g_ctxh);
    cudaGetSymbolAddress((void**)&ctxl,  g_ctxl);
    cudaGetSymbolAddress((void**)&qhp,   g_qh);
    cudaGetSymbolAddress((void**)&qlp,   g_ql);
    cudaGetSymbolAddress((void**)&khp,   g_kh);
    cudaGetSymbolAddress((void**)&klp,   g_kl);
    cudaGetSymbolAddress((void**)&vhp,   g_vh);
    cudaGetSymbolAddress((void**)&vlp,   g_vl);
    cudaGetSymbolAddress((void**)&wpreh, g_wpreh);
    cudaGetSymbolAddress((void**)&wprel, g_wprel);
    cudaGetSymbolAddress((void**)&wqh,   g_wqh);
    cudaGetSymbolAddress((void**)&wql,   g_wql);
    cudaGetSymbolAddress((void**)&wkh,   g_wkh);
    cudaGetSymbolAddress((void**)&wkl,   g_wkl);
    cudaGetSymbolAddress((void**)&wvh,   g_wvh);
    cudaGetSymbolAddress((void**)&wvl,   g_wvl);
    cudaGetSymbolAddress((void**)&wph,   g_wph);
    cudaGetSymbolAddress((void**)&wpl,   g_wpl);

    cudaFuncSetAttribute(hmma_qkv,  cudaFuncAttributeMaxDynamicSharedMemorySize, SMEM_HMMA);
    cudaFuncSetAttribute(hmma_gemm, cudaFuncAttributeMaxDynamicSharedMemorySize, SMEM_HMMA);
    cudaFuncSetAttribute(fattn,     cudaFuncAttributeMaxDynamicSharedMemorySize, SMEM_FATT);

    // ---- prep: all 5 weight splits in one launch + x split ----
    dim3 wst(32, 8), wsg(32, 32, 5);
    wsplit_T5<<<wsg, wst>>>(Wpre, Wq, Wk, Wv, Wproj,
                            wpreh, wprel, wqh, wql, wkh, wkl, wvh, wvl, wph, wpl);
    const int n2 = MROWS * CC / 2;
    split2<<<(n2 + 255) / 256, 256>>>((const float2*)x,
        (__nv_bfloat162*)xh, (__nv_bfloat162*)xl, n2);

    // ---- merged pre/Q/K/V GEMM ----
    dim3 mb(256);
    dim3 gqkv(32, MROWS / 128, 1);               // (32, 32)
    hmma_qkv<<<gqkv, mb, SMEM_HMMA>>>(xh, xl,
        wpreh, wprel, wqh, wql, wkh, wkl, wvh, wvl, bpre,
        preh, prel, qhp, qlp, khp, klp, vhp, vlp);

    // ---- logits GEMM (symmetric: 36 upper-tri tiles/batch) ----
    dim3 glog(36, 1, BB);
    hmma_gemm<<<glog, mb, SMEM_HMMA>>>(preh, prel, preh, prel, nullptr, nullptr,
                                       lgp, EPI_LOGITS,
                                       (long long)NN * CC, (long long)NN * CC);

    // ---- HMMA flash attention (128-query tiles) ----
    dim3 ga(NN / 128, BB * HH);
    fattn<<<ga, 256, SMEM_FATT>>>(qhp, qlp, khp, klp, vhp, vlp, lgp, pi,
                                  ctxh, ctxl);

    // ---- projection + residual ----
    dim3 gl(CC / 128, MROWS / 128, 1);
    hmma_gemm<<<gl, mb, SMEM_HMMA>>>(ctxh, ctxl, wph, wpl, bproj, x,
                                     out, EPI_RESID, 0, 0);
}